// round 12
// baseline (speedup 1.0000x reference)
#include <cuda_runtime.h>
#include <cuda_bf16.h>
#include <math.h>
#include <stdint.h>

#define S_LEN 5120
#define T_LEN 1024
#define SH_LEN 4096
#define H_DIM 512
#define D_DIM 608
#define G_DIM 2048
#define LOC_N 50000
#define FC_K 1088
#define DU_DIM 64
#define NB 64                 // fallback LSTM blocks per group
#define CL 16                 // cluster size for DSMEM LSTM
#define SENT_U 0x3FC00000u    // 1.5f fp32 sentinel (fallback path)
#define SENT32 0x3FC03FC0u    // bf16x2 {1.5,1.5} sentinel (cluster path)

// ---------------- scratch (device globals; no allocation allowed) ----------
__device__ float g_pre_enc[SH_LEN * G_DIM];
__device__ float g_pre_dec[T_LEN * G_DIM];
__device__ float g_hh[SH_LEN * H_DIM];     // fallback path only
__device__ float g_hd[T_LEN * H_DIM];      // fallback path only
__device__ float g_attn[(size_t)T_LEN * SH_LEN];
__device__ float g_ctx[T_LEN * H_DIM];
__device__ float g_y[(size_t)T_LEN * LOC_N];

// bf16 operand buffers
__device__ __nv_bfloat16 g_xb[S_LEN * D_DIM];
__device__ __nv_bfloat16 g_wihb_e[G_DIM * D_DIM];
__device__ __nv_bfloat16 g_wihb_d[G_DIM * D_DIM];
__device__ __nv_bfloat16 g_fcWb[(size_t)LOC_N * FC_K];
__device__ __nv_bfloat16 g_hhb[SH_LEN * H_DIM];
__device__ __nv_bfloat16 g_hdb[T_LEN * H_DIM];
__device__ __nv_bfloat16 g_hhTb[H_DIM * SH_LEN];
__device__ __nv_bfloat16 g_attnb[(size_t)T_LEN * SH_LEN];
__device__ __nv_bfloat16 g_outb[T_LEN * FC_K];

// ------- embedding gather -> bf16 directly (+ sentinel fill for fallback) --
__global__ void embed_kernel(const int* __restrict__ loc, const int* __restrict__ tim,
                             const int* __restrict__ clu,
                             const float* __restrict__ el, const float* __restrict__ et,
                             const float* __restrict__ ec) {
    int s = blockIdx.x, t = threadIdx.x;
    __nv_bfloat16* xrow = &g_xb[(size_t)s * D_DIM];
    if (t < 128) {
        float4 sv = make_float4(1.5f, 1.5f, 1.5f, 1.5f);
        if (s < SH_LEN) *(float4*)&g_hh[(size_t)s * H_DIM + t * 4] = sv;
        if (s < T_LEN)  *(float4*)&g_hd[(size_t)s * H_DIM + t * 4] = sv;
        float4 v = *(const float4*)&el[(size_t)loc[s] * 512 + t * 4];
        __nv_bfloat162 o[2];
        o[0] = __float22bfloat162_rn(make_float2(v.x, v.y));
        o[1] = __float22bfloat162_rn(make_float2(v.z, v.w));
        *(uint2*)&xrow[t * 4] = *(uint2*)o;
    } else if (t < 136) {
        int j = t - 128;
        float4 v = *(const float4*)&et[(size_t)tim[s] * 32 + j * 4];
        __nv_bfloat162 o[2];
        o[0] = __float22bfloat162_rn(make_float2(v.x, v.y));
        o[1] = __float22bfloat162_rn(make_float2(v.z, v.w));
        *(uint2*)&xrow[512 + j * 4] = *(uint2*)o;
    } else if (t < 152) {
        int j = t - 136;
        float4 v = *(const float4*)&ec[(size_t)clu[s] * 64 + j * 4];
        __nv_bfloat162 o[2];
        o[0] = __float22bfloat162_rn(make_float2(v.x, v.y));
        o[1] = __float22bfloat162_rn(make_float2(v.z, v.w));
        *(uint2*)&xrow[544 + j * 4] = *(uint2*)o;
    }
}

// ---------------- fp32 -> bf16 conversions ----------------
__global__ void f2b16_kernel(const float* __restrict__ in, __nv_bfloat16* __restrict__ out,
                             int n) {
    int i = (blockIdx.x * blockDim.x + threadIdx.x) * 16;
    if (i < n) {
#pragma unroll
        for (int h = 0; h < 2; h++) {
            float4 v0 = *(const float4*)&in[i + h * 8];
            float4 v1 = *(const float4*)&in[i + h * 8 + 4];
            __nv_bfloat162 o[4];
            o[0] = __float22bfloat162_rn(make_float2(v0.x, v0.y));
            o[1] = __float22bfloat162_rn(make_float2(v0.z, v0.w));
            o[2] = __float22bfloat162_rn(make_float2(v1.x, v1.y));
            o[3] = __float22bfloat162_rn(make_float2(v1.z, v1.w));
            *(int4*)&out[i + h * 8] = *(int4*)o;
        }
    }
}

__global__ void f2bw_kernel(const float* __restrict__ e, const float* __restrict__ d) {
    int bid = blockIdx.x;
    const float* in;
    __nv_bfloat16* out;
    if (bid < 608) { in = e; out = g_wihb_e; }
    else { in = d; out = g_wihb_d; bid -= 608; }
    int i = (bid * 256 + threadIdx.x) * 8;
    float4 v0 = *(const float4*)&in[i];
    float4 v1 = *(const float4*)&in[i + 4];
    __nv_bfloat162 o[4];
    o[0] = __float22bfloat162_rn(make_float2(v0.x, v0.y));
    o[1] = __float22bfloat162_rn(make_float2(v0.z, v0.w));
    o[2] = __float22bfloat162_rn(make_float2(v1.x, v1.y));
    o[3] = __float22bfloat162_rn(make_float2(v1.z, v1.w));
    *(int4*)&out[i] = *(int4*)o;
}

// ---------------- bf16 tensor-core GEMM body: C = A @ B^T + bias ---------
__device__ __forceinline__ void ldsm4(uint32_t& r0, uint32_t& r1, uint32_t& r2,
                                      uint32_t& r3, uint32_t a) {
    asm volatile("ldmatrix.sync.aligned.m8n8.x4.shared.b16 {%0,%1,%2,%3}, [%4];"
                 : "=r"(r0), "=r"(r1), "=r"(r2), "=r"(r3) : "r"(a));
}
__device__ __forceinline__ void mma16816(float* c, const uint32_t* a, const uint32_t* b) {
    asm volatile(
        "mma.sync.aligned.m16n8k16.row.col.f32.bf16.bf16.f32 "
        "{%0,%1,%2,%3},{%4,%5,%6,%7},{%8,%9},{%0,%1,%2,%3};"
        : "+f"(c[0]), "+f"(c[1]), "+f"(c[2]), "+f"(c[3])
        : "r"(a[0]), "r"(a[1]), "r"(a[2]), "r"(a[3]), "r"(b[0]), "r"(b[1]));
}

__device__ __forceinline__ void gemm_body(
    const __nv_bfloat16* __restrict__ A, const __nv_bfloat16* __restrict__ B,
    float* __restrict__ C, const float* __restrict__ bias1,
    const float* __restrict__ bias2, int m0, int n0, int N, int K)
{
    __shared__ __nv_bfloat16 As[2][128][40];
    __shared__ __nv_bfloat16 Bs[2][128][40];
    const int tid = threadIdx.x, lane = tid & 31, warp = tid >> 5;
    const int wm = warp & 1, wn = warp >> 1;
    const int lr = tid >> 2;
    const int lc = (tid & 3) << 3;
    const int grp = lane >> 3, lrr = lane & 7;

    float acc[4][4][4];
#pragma unroll
    for (int i = 0; i < 4; i++)
#pragma unroll
        for (int j = 0; j < 4; j++)
#pragma unroll
            for (int r = 0; r < 4; r++) acc[i][j][r] = 0.f;

    int4 ra0, ra1, rb0, rb1;
    const int KT = K >> 5;
    const int4 zero4 = make_int4(0, 0, 0, 0);

    {
        const __nv_bfloat16* Ap = A + (size_t)(m0 + lr) * K + lc;
        ra0 = *(const int4*)Ap;
        ra1 = *(const int4*)(Ap + (size_t)64 * K);
        int nr0 = n0 + lr, nr1 = nr0 + 64;
        rb0 = (nr0 < N) ? *(const int4*)(B + (size_t)nr0 * K + lc) : zero4;
        rb1 = (nr1 < N) ? *(const int4*)(B + (size_t)nr1 * K + lc) : zero4;
    }
    *(int4*)&As[0][lr][lc] = ra0;
    *(int4*)&As[0][lr + 64][lc] = ra1;
    *(int4*)&Bs[0][lr][lc] = rb0;
    *(int4*)&Bs[0][lr + 64][lc] = rb1;
    __syncthreads();

    for (int kt = 0; kt < KT; kt++) {
        const int buf = kt & 1;
        if (kt + 1 < KT) {
            const int k0 = (kt + 1) << 5;
            const __nv_bfloat16* Ap = A + (size_t)(m0 + lr) * K + k0 + lc;
            ra0 = *(const int4*)Ap;
            ra1 = *(const int4*)(Ap + (size_t)64 * K);
            int nr0 = n0 + lr, nr1 = nr0 + 64;
            rb0 = (nr0 < N) ? *(const int4*)(B + (size_t)nr0 * K + k0 + lc) : zero4;
            rb1 = (nr1 < N) ? *(const int4*)(B + (size_t)nr1 * K + k0 + lc) : zero4;
        }
#pragma unroll
        for (int kk = 0; kk < 2; kk++) {
            const int kb = kk << 4;
            uint32_t af[4][4], bf[4][2];
#pragma unroll
            for (int mt = 0; mt < 4; mt++) {
                int row = wm * 64 + mt * 16 + ((grp & 1) << 3) + lrr;
                int col = kb + ((grp >> 1) << 3);
                ldsm4(af[mt][0], af[mt][1], af[mt][2], af[mt][3],
                      (uint32_t)__cvta_generic_to_shared(&As[buf][row][col]));
            }
#pragma unroll
            for (int nt2 = 0; nt2 < 2; nt2++) {
                int row = wn * 32 + nt2 * 16 + ((grp >> 1) << 3) + lrr;
                int col = kb + ((grp & 1) << 3);
                uint32_t r0, r1, r2, r3;
                ldsm4(r0, r1, r2, r3,
                      (uint32_t)__cvta_generic_to_shared(&Bs[buf][row][col]));
                bf[nt2 * 2][0] = r0; bf[nt2 * 2][1] = r1;
                bf[nt2 * 2 + 1][0] = r2; bf[nt2 * 2 + 1][1] = r3;
            }
#pragma unroll
            for (int mt = 0; mt < 4; mt++)
#pragma unroll
                for (int nt = 0; nt < 4; nt++)
                    mma16816(acc[mt][nt], af[mt], bf[nt]);
        }
        if (kt + 1 < KT) {
            const int nb = buf ^ 1;
            *(int4*)&As[nb][lr][lc] = ra0;
            *(int4*)&As[nb][lr + 64][lc] = ra1;
            *(int4*)&Bs[nb][lr][lc] = rb0;
            *(int4*)&Bs[nb][lr + 64][lc] = rb1;
            __syncthreads();
        }
    }

#pragma unroll
    for (int nt = 0; nt < 4; nt++) {
        int col = n0 + wn * 32 + nt * 8 + ((lane & 3) << 1);
        if (col >= N) continue;
        float b0 = 0.f, b1 = 0.f;
        if (bias1) { b0 += bias1[col]; b1 += bias1[col + 1]; }
        if (bias2) { b0 += bias2[col]; b1 += bias2[col + 1]; }
#pragma unroll
        for (int mt = 0; mt < 4; mt++) {
            int row = m0 + wm * 64 + mt * 16 + (lane >> 2);
            float2 v0 = make_float2(acc[mt][nt][0] + b0, acc[mt][nt][1] + b1);
            float2 v1 = make_float2(acc[mt][nt][2] + b0, acc[mt][nt][3] + b1);
            *(float2*)&C[(size_t)row * N + col] = v0;
            *(float2*)&C[(size_t)(row + 8) * N + col] = v1;
        }
    }
}

__global__ void __launch_bounds__(256) gemm_tc(
    const __nv_bfloat16* __restrict__ A, const __nv_bfloat16* __restrict__ B,
    float* __restrict__ C, const float* __restrict__ bias1,
    const float* __restrict__ bias2, int N, int K)
{
    gemm_body(A, B, C, bias1, bias2, blockIdx.y * 128, blockIdx.x * 128, N, K);
}

// M-fastest grid ordering (FC: consecutive blocks share the B N-tile in L2)
__global__ void __launch_bounds__(256) gemm_tc_mfirst(
    const __nv_bfloat16* __restrict__ A, const __nv_bfloat16* __restrict__ B,
    float* __restrict__ C, const float* __restrict__ bias1, int N, int K)
{
    gemm_body(A, B, C, bias1, nullptr, blockIdx.x * 128, blockIdx.y * 128, N, K);
}

__global__ void __launch_bounds__(256) gemm_pre(
    float* __restrict__ Ce, float* __restrict__ Cd,
    const float* __restrict__ ebih, const float* __restrict__ ebhh,
    const float* __restrict__ dbih, const float* __restrict__ dbhh)
{
    int by = blockIdx.y;
    if (by < 32)
        gemm_body(g_xb, g_wihb_e, Ce, ebih, ebhh, by * 128, blockIdx.x * 128,
                  G_DIM, D_DIM);
    else
        gemm_body(g_xb + (size_t)SH_LEN * D_DIM, g_wihb_d, Cd, dbih, dbhh,
                  (by - 32) * 128, blockIdx.x * 128, G_DIM, D_DIM);
}

// ---------------- LSTM helpers ----------------
__device__ __forceinline__ float tanhap(float x) {
    float y; asm("tanh.approx.f32 %0, %1;" : "=f"(y) : "f"(x)); return y;
}
__device__ __forceinline__ float sigap(float x) {
    return 0.5f * tanhap(0.5f * x) + 0.5f;
}
__device__ __forceinline__ void ffma2(uint64_t& acc, uint64_t a, uint64_t b) {
    asm("fma.rn.f32x2 %0, %1, %2, %0;" : "+l"(acc) : "l"(a), "l"(b));
}
__device__ __forceinline__ uint32_t packbf(float2 v) {
    __nv_bfloat162 b = __float22bfloat162_rn(v);
    return *(uint32_t*)&b;
}

// ============ cluster DSMEM LSTM (proven R9 version, byte-identical) =======
// CTA rank r owns units [32r, 32r+32) = 128 gate rows. Warp w: local rows
// [16w,16w+16); A-fragments in registers. warp0 does gates+publish while
// warps 1-7 race ahead. 4-slot sentinel ring -> reset folds behind S1
// (2 block barriers per step). Publish: 32 lanes x 8 remote stores.
__global__ void __launch_bounds__(256, 1) lstm_cluster_kernel(
    const float* __restrict__ preE, const float* __restrict__ WhhE,
    const float* __restrict__ preD, const float* __restrict__ WhhD)
{
    __shared__ __align__(16) unsigned int hbuf[4][256];   // 512 bf16 units/slot
    __shared__ float gsm[128];

    const int tid = threadIdx.x, lane = tid & 31, warp = tid >> 5;
    uint32_t rank;
    asm("mov.u32 %0, %%cluster_ctarank;" : "=r"(rank));
    const bool enc = (blockIdx.x >> 4) == 0;
    const float* pre = enc ? preE : preD;
    const float* Whh = enc ? WhhE : WhhD;
    __nv_bfloat16* hb = enc ? g_hhb : g_hdb;
    const int T = enc ? SH_LEN : T_LEN;

    // init all 4 sentinel slots
#pragma unroll
    for (int s = 0; s < 4; s++) hbuf[s][tid] = SENT32;

    // load A fragments: 32 k-chunks x 4 regs (m16n8k16 A layout, bf16)
    uint32_t aW[32][4];
    {
        int i0 = lane >> 2;
        int r0 = 16 * warp + i0, r1 = r0 + 8;
        const float* W0 = Whh + (size_t)((r0 >> 5) * H_DIM + rank * 32 + (r0 & 31)) * H_DIM;
        const float* W1 = Whh + (size_t)((r1 >> 5) * H_DIM + rank * 32 + (r1 & 31)) * H_DIM;
        int kb = (lane & 3) * 2;
#pragma unroll
        for (int kc = 0; kc < 32; kc++) {
            int k = kc * 16 + kb;
            aW[kc][0] = packbf(*(const float2*)&W0[k]);
            aW[kc][1] = packbf(*(const float2*)&W1[k]);
            aW[kc][2] = packbf(*(const float2*)&W0[k + 8]);
            aW[kc][3] = packbf(*(const float2*)&W1[k + 8]);
        }
    }

    // cluster barrier: all smem sentinel-initialized before any remote store
    asm volatile("barrier.cluster.arrive.aligned;" ::: "memory");
    asm volatile("barrier.cluster.wait.aligned;" ::: "memory");

    float creg = 0.f;
    float pv0 = 0.f, pv1 = 0.f, pv2 = 0.f, pv3 = 0.f;
    if (warp == 0) {
        int u = rank * 32 + lane;
        pv0 = __ldg(&pre[0 * H_DIM + u]);
        pv1 = __ldg(&pre[1 * H_DIM + u]);
        pv2 = __ldg(&pre[2 * H_DIM + u]);
        pv3 = __ldg(&pre[3 * H_DIM + u]);
    }

    for (int t = 0; t < T; t++) {
        const int sl = t & 3, sp = (t - 1) & 3;

        if (t > 0) {    // wait for h(t-1): every thread polls its own word
            volatile unsigned int* hv = &hbuf[sp][tid];
            while (*hv == SENT32) { }
        }
        __syncthreads();   // S1: slot sp fully delivered, visible block-wide

        // reset slot consumed at step t-1 (safe: next write is h(t+2),
        // causally gated by our h(t+1) publish which follows this reset)
        if (t > 1) hbuf[(t - 2) & 3][tid] = SENT32;

        float v0 = 0.f, v1 = 0.f;
        if (t > 0) {
            float c[4][4];
#pragma unroll
            for (int g = 0; g < 4; g++)
#pragma unroll
                for (int j = 0; j < 4; j++) c[g][j] = 0.f;
#pragma unroll
            for (int kc = 0; kc < 32; kc++) {
                uint32_t b[2];
                b[0] = hbuf[sp][kc * 8 + (lane & 3)];
                b[1] = hbuf[sp][kc * 8 + 4 + (lane & 3)];
                mma16816(c[kc >> 3], aW[kc], b);
            }
            v0 = c[0][0] + c[1][0] + c[2][0] + c[3][0];
            v1 = c[0][2] + c[1][2] + c[2][2] + c[3][2];
        }
        if ((lane & 3) == 0) {
            gsm[16 * warp + (lane >> 2)] = v0;
            gsm[16 * warp + 8 + (lane >> 2)] = v1;
        }
        __syncthreads();   // S3: gsm ready

        if (warp == 0) {
            float ig = sigap(gsm[lane] + pv0);
            float fg = sigap(gsm[32 + lane] + pv1);
            float gg = tanhap(gsm[64 + lane] + pv2);
            float og = sigap(gsm[96 + lane] + pv3);
            float cc = fg * creg + ig * gg;
            creg = cc;
            float h = og * tanhap(cc);
            __nv_bfloat16 hbf = __float2bfloat16(h);
            unsigned int mine = *(unsigned short*)&hbf;
            unsigned int nbv = __shfl_down_sync(0xffffffffu, mine, 1);
            unsigned int word = mine | (nbv << 16);           // valid on even lanes
            unsigned int wAll = __shfl_sync(0xffffffffu, word, lane & 30);
            if (t + 1 < T) {
                // 32 lanes x 8 ranks: lane pair (2k,2k+1) shares word k
                int rbase = (lane & 1) * 8;
                uint32_t laddr = (uint32_t)__cvta_generic_to_shared(
                    &hbuf[sl][rank * 16 + (lane >> 1)]);
#pragma unroll
                for (int pr = 0; pr < 8; pr++) {
                    uint32_t pa;
                    asm("mapa.shared::cluster.u32 %0, %1, %2;"
                        : "=r"(pa) : "r"(laddr), "r"(rbase + pr));
                    asm volatile("st.shared::cluster.u32 [%0], %1;"
                                 :: "r"(pa), "r"(wAll) : "memory");
                }
            }
            // side outputs (off critical path)
            int gu = rank * 32 + lane;
            hb[(size_t)t * H_DIM + gu] = hbf;
            if (enc) g_hhTb[(size_t)gu * SH_LEN + t] = hbf;
            if (t + 1 < T) {
                const float* pn = pre + (size_t)(t + 1) * G_DIM + gu;
                pv0 = __ldg(&pn[0 * H_DIM]);
                pv1 = __ldg(&pn[1 * H_DIM]);
                pv2 = __ldg(&pn[2 * H_DIM]);
                pv3 = __ldg(&pn[3 * H_DIM]);
            }
        }
    }

    asm volatile("barrier.cluster.arrive.aligned;" ::: "memory");
    asm volatile("barrier.cluster.wait.aligned;" ::: "memory");
}

// ============ fallback: L2 sentinel LSTM (R6 design, proven) ==============
__global__ void __launch_bounds__(256) lstm_fused_kernel(
    const float* __restrict__ preE, const float* __restrict__ WhhE, float* __restrict__ histE,
    const float* __restrict__ preD, const float* __restrict__ WhhD, float* __restrict__ histD)
{
    __shared__ __align__(16) float hs[H_DIM];
    __shared__ float gs[32];
    __shared__ float ps[32];

    const bool enc = blockIdx.x < NB;
    const float* pre  = enc ? preE : preD;
    const float* Whh  = enc ? WhhE : WhhD;
    float* hist       = enc ? histE : histD;
    __nv_bfloat16* hb = enc ? g_hhb : g_hdb;
    const int T       = enc ? SH_LEN : T_LEN;

    const int b = enc ? blockIdx.x : blockIdx.x - NB;
    const int tid = threadIdx.x, lane = tid & 31, warp = tid >> 5;

    uint64_t w2[4][8];
#pragma unroll
    for (int rr = 0; rr < 4; rr++) {
        int r = warp * 4 + rr, g = r >> 3, u = r & 7;
        int grow = g * H_DIM + b * 8 + u;
        const ulonglong2* src = (const ulonglong2*)&Whh[(size_t)grow * H_DIM + lane * 16];
#pragma unroll
        for (int j = 0; j < 4; j++) {
            ulonglong2 v = src[j];
            w2[rr][2 * j] = v.x; w2[rr][2 * j + 1] = v.y;
        }
    }
    float creg = 0.f;

    float psv = 0.f;
    if (tid < 32)
        psv = __ldg(&pre[(tid >> 3) * H_DIM + b * 8 + (tid & 7)]);

    for (int t = 0; t < T; t++) {
        if (t == 0) {
            hs[2 * tid] = 0.f; hs[2 * tid + 1] = 0.f;
        } else {
            const float* src = &hist[(size_t)(t - 1) * H_DIM + 2 * tid];
            float hx, hy;
            unsigned int ux, uy;
            do {
                asm volatile("ld.volatile.global.v2.f32 {%0,%1}, [%2];"
                             : "=f"(hx), "=f"(hy) : "l"(src) : "memory");
                ux = __float_as_uint(hx); uy = __float_as_uint(hy);
            } while (ux == SENT_U || uy == SENT_U);
            hs[2 * tid] = hx; hs[2 * tid + 1] = hy;
        }
        if (tid < 32) ps[tid] = psv;
        __syncthreads();

        if (tid < 32 && t + 1 < T)
            psv = __ldg(&pre[(size_t)(t + 1) * G_DIM + (tid >> 3) * H_DIM + b * 8 + (tid & 7)]);

        uint64_t acc2[4] = {0ull, 0ull, 0ull, 0ull};
        const uint64_t* h2p = (const uint64_t*)&hs[lane * 16];
#pragma unroll
        for (int j = 0; j < 8; j++) {
            uint64_t h2 = h2p[j];
#pragma unroll
            for (int rr = 0; rr < 4; rr++) ffma2(acc2[rr], w2[rr][j], h2);
        }
        float acc[4];
#pragma unroll
        for (int rr = 0; rr < 4; rr++) {
            union { uint64_t u; float2 f; } c; c.u = acc2[rr];
            acc[rr] = c.f.x + c.f.y;
        }
#pragma unroll
        for (int o = 16; o > 0; o >>= 1) {
#pragma unroll
            for (int rr = 0; rr < 4; rr++)
                acc[rr] += __shfl_xor_sync(0xffffffffu, acc[rr], o);
        }
        if (lane == 0) {
#pragma unroll
            for (int rr = 0; rr < 4; rr++)
                gs[warp * 4 + rr] = acc[rr] + ps[warp * 4 + rr];
        }
        __syncthreads();

        if (warp == 0 && lane < 8) {
            float ig = sigap(gs[lane]);
            float fg = sigap(gs[8 + lane]);
            float gg = tanhap(gs[16 + lane]);
            float og = sigap(gs[24 + lane]);
            float c = fg * creg + ig * gg;
            creg = c;
            float h = og * tanhap(c);
            int gu = b * 8 + lane;
            __stcg(&hist[(size_t)t * H_DIM + gu], h);
            hb[(size_t)t * H_DIM + gu] = __float2bfloat16(h);
            if (enc) g_hhTb[(size_t)gu * SH_LEN + t] = __float2bfloat16(h);
        }
    }
}

// ---------------- reductions ----------------
__device__ __forceinline__ float block_max_256(float v, float* red) {
#pragma unroll
    for (int o = 16; o > 0; o >>= 1) v = fmaxf(v, __shfl_xor_sync(0xffffffffu, v, o));
    if ((threadIdx.x & 31) == 0) red[threadIdx.x >> 5] = v;
    __syncthreads();
    if (threadIdx.x < 32) {
        float x = (threadIdx.x < 8) ? red[threadIdx.x] : -1e30f;
#pragma unroll
        for (int o = 4; o > 0; o >>= 1) x = fmaxf(x, __shfl_xor_sync(0xffffffffu, x, o));
        if (threadIdx.x == 0) red[0] = x;
    }
    __syncthreads();
    float r = red[0];
    __syncthreads();
    return r;
}

__device__ __forceinline__ float block_sum_256(float v, float* red) {
#pragma unroll
    for (int o = 16; o > 0; o >>= 1) v += __shfl_xor_sync(0xffffffffu, v, o);
    if ((threadIdx.x & 31) == 0) red[threadIdx.x >> 5] = v;
    __syncthreads();
    if (threadIdx.x < 32) {
        float x = (threadIdx.x < 8) ? red[threadIdx.x] : 0.f;
#pragma unroll
        for (int o = 4; o > 0; o >>= 1) x += __shfl_xor_sync(0xffffffffu, x, o);
        if (threadIdx.x == 0) red[0] = x;
    }
    __syncthreads();
    float r = red[0];
    __syncthreads();
    return r;
}

// softmax over rows of g_attn -> bf16 g_attnb
__global__ void __launch_bounds__(256) softmax_kernel() {
    __shared__ float red[8];
    const int row = blockIdx.x, tid = threadIdx.x;
    const float* X = &g_attn[(size_t)row * SH_LEN];
    __nv_bfloat16* O = &g_attnb[(size_t)row * SH_LEN];
    float v[16];
    float m = -1e30f;
#pragma unroll
    for (int j = 0; j < 16; j++) { v[j] = X[tid + j * 256]; m = fmaxf(m, v[j]); }
    m = block_max_256(m, red);
    float s = 0.f;
#pragma unroll
    for (int j = 0; j < 16; j++) { v[j] = expf(v[j] - m); s += v[j]; }
    s = block_sum_256(s, red);
    float inv = 1.f / s;
#pragma unroll
    for (int j = 0; j < 16; j++) O[tid + j * 256] = __float2bfloat16(v[j] * inv);
}

// log_softmax over rows of g_y -> out (online, 512 thr)
__global__ void __launch_bounds__(512) logsoftmax_kernel(float* __restrict__ out) {
    __shared__ float redm[16], reds[16];
    const int row = blockIdx.x, tid = threadIdx.x;
    const int lane = tid & 31, warp = tid >> 5;
    const float* Y = &g_y[(size_t)row * LOC_N];
    float* O = &out[(size_t)row * LOC_N];

    float m = -1e30f, s = 0.f;
    for (int c = tid * 4; c < LOC_N; c += 2048) {
        float4 v = *(const float4*)&Y[c];
        float ml = fmaxf(fmaxf(v.x, v.y), fmaxf(v.z, v.w));
        if (ml > m) { s *= __expf(m - ml); m = ml; }
        s += __expf(v.x - m) + __expf(v.y - m) + __expf(v.z - m) + __expf(v.w - m);
    }
#pragma unroll
    for (int o = 16; o > 0; o >>= 1) {
        float m2 = __shfl_xor_sync(0xffffffffu, m, o);
        float s2 = __shfl_xor_sync(0xffffffffu, s, o);
        float M = fmaxf(m, m2);
        s = s * __expf(m - M) + s2 * __expf(m2 - M);
        m = M;
    }
    if (lane == 0) { redm[warp] = m; reds[warp] = s; }
    __syncthreads();
    if (tid < 32) {
        float mm = (tid < 16) ? redm[tid] : -1e30f;
        float ss = (tid < 16) ? reds[tid] : 0.f;
#pragma unroll
        for (int o = 8; o > 0; o >>= 1) {
            float m2 = __shfl_xor_sync(0xffffffffu, mm, o);
            float s2 = __shfl_xor_sync(0xffffffffu, ss, o);
            float M = fmaxf(mm, m2);
            ss = ss * __expf(mm - M) + s2 * __expf(m2 - M);
            mm = M;
        }
        if (tid == 0) { redm[0] = mm; reds[0] = ss; }
    }
    __syncthreads();
    float ls = redm[0] + logf(reds[0]);
    for (int c = tid * 4; c < LOC_N; c += 2048) {
        float4 v = *(const float4*)&Y[c];
        v.x -= ls; v.y -= ls; v.z -= ls; v.w -= ls;
        *(float4*)&O[c] = v;
    }
}

// concat [hd(bf16) | ctx | uid_emb] -> g_outb bf16 [T_LEN, FC_K]
__global__ void concat_kernel(const float* __restrict__ emb_uid, const int* __restrict__ uid) {
    int row = blockIdx.x, t = threadIdx.x;
    if (t < 128) {
        uint2 v = *(const uint2*)&g_hdb[(size_t)row * H_DIM + t * 4];
        *(uint2*)&g_outb[(size_t)row * FC_K + t * 4] = v;
    } else {
        float4 v;
        if (t < 256) v = *(const float4*)&g_ctx[(size_t)row * H_DIM + (t - 128) * 4];
        else         v = *(const float4*)&emb_uid[(size_t)uid[0] * DU_DIM + (t - 256) * 4];
        __nv_bfloat162 o[2];
        o[0] = __float22bfloat162_rn(make_float2(v.x, v.y));
        o[1] = __float22bfloat162_rn(make_float2(v.z, v.w));
        *(uint2*)&g_outb[(size_t)row * FC_K + t * 4] = *(uint2*)o;
    }
}

// ---------------- host ----------------
extern "C" void kernel_launch(void* const* d_in, const int* in_sizes, int n_in,
                              void* d_out, int out_size) {
    const int* loc = (const int*)d_in[0];
    const int* tim = (const int*)d_in[1];
    const int* clu = (const int*)d_in[2];
    const int* uid = (const int*)d_in[3];
    const float* emb_loc = (const float*)d_in[5];
    const float* emb_tim = (const float*)d_in[6];
    const float* emb_clu = (const float*)d_in[7];
    const float* emb_uid = (const float*)d_in[8];
    const float* eWih = (const float*)d_in[9];
    const float* eWhh = (const float*)d_in[10];
    const float* ebih = (const float*)d_in[11];
    const float* ebhh = (const float*)d_in[12];
    const float* dWih = (const float*)d_in[13];
    const float* dWhh = (const float*)d_in[14];
    const float* dbih = (const float*)d_in[15];
    const float* dbhh = (const float*)d_in[16];
    const float* fcW = (const float*)d_in[17];
    const float* fcb = (const float*)d_in[18];
    float* out = (float*)d_out;

    float *ppe, *ppd, *phh, *phd, *pat, *pcx, *py;
    cudaGetSymbolAddress((void**)&ppe, g_pre_enc);
    cudaGetSymbolAddress((void**)&ppd, g_pre_dec);
    cudaGetSymbolAddress((void**)&phh, g_hh);
    cudaGetSymbolAddress((void**)&phd, g_hd);
    cudaGetSymbolAddress((void**)&pat, g_attn);
    cudaGetSymbolAddress((void**)&pcx, g_ctx);
    cudaGetSymbolAddress((void**)&py,  g_y);
    __nv_bfloat16 *pfcb, *phhb, *phdb, *phhTb, *patb, *potb;
    cudaGetSymbolAddress((void**)&pfcb,  g_fcWb);
    cudaGetSymbolAddress((void**)&phhb,  g_hhb);
    cudaGetSymbolAddress((void**)&phdb,  g_hdb);
    cudaGetSymbolAddress((void**)&phhTb, g_hhTb);
    cudaGetSymbolAddress((void**)&patb,  g_attnb);
    cudaGetSymbolAddress((void**)&potb,  g_outb);

    // 0. embed -> bf16 x; sentinel fill (for fallback path)
    embed_kernel<<<S_LEN, 152>>>(loc, tim, clu, emb_loc, emb_tim, emb_clu);
    // 1. Wih conversions
    f2bw_kernel<<<1216, 256>>>(eWih, dWih);
    // 2. both input projections
    gemm_pre<<<dim3(G_DIM / 128, 40), 256>>>(ppe, ppd, ebih, ebhh, dbih, dbhh);

    // 3. LSTMs: cluster-DSMEM path if 16-CTA clusters supported, else L2 path
    cudaLaunchAttribute cattr[1];
    cattr[0].id = cudaLaunchAttributeClusterDimension;
    cattr[0].val.clusterDim.x = CL; cattr[0].val.clusterDim.y = 1;
    cattr[0].val.clusterDim.z = 1;
    cudaLaunchConfig_t cfg = {};
    cfg.gridDim = dim3(2 * CL, 1, 1);
    cfg.blockDim = dim3(256, 1, 1);
    cfg.dynamicSmemBytes = 0;
    cfg.stream = 0;
    cfg.attrs = cattr;
    cfg.numAttrs = 1;
    cudaError_t ra = cudaFuncSetAttribute(
        lstm_cluster_kernel, cudaFuncAttributeNonPortableClusterSizeAllowed, 1);
    int ncl = 0;
    cudaError_t rb = cudaOccupancyMaxActiveClusters(&ncl, lstm_cluster_kernel, &cfg);
    (void)cudaGetLastError();
    if (ra == cudaSuccess && rb == cudaSuccess && ncl >= 2) {
        cudaLaunchKernelEx(&cfg, lstm_cluster_kernel, (const float*)ppe, eWhh,
                           (const float*)ppd, dWhh);
    } else {
        lstm_fused_kernel<<<2 * NB, 256>>>(ppe, eWhh, phh, ppd, dWhh, phd);
    }

    // 4. fcW conversion
    f2b16_kernel<<<(LOC_N * FC_K / 16 + 255) / 256, 256>>>(fcW, pfcb, LOC_N * FC_K);
    // 5. attention scores = hd @ hh^T
    gemm_tc<<<dim3(SH_LEN / 128, T_LEN / 128), 256>>>(phdb, phhb, pat, nullptr, nullptr,
                                                      SH_LEN, H_DIM);
    // 6. softmax rows -> bf16
    softmax_kernel<<<T_LEN, 256>>>();
    // 7. context = attn @ hh
    gemm_tc<<<dim3(H_DIM / 128, T_LEN / 128), 256>>>(patb, phhTb, pcx, nullptr, nullptr,
                                                     H_DIM, SH_LEN);
    // 8. concat -> bf16
    concat_kernel<<<T_LEN, 272>>>(emb_uid, uid);
    // 9. FC: y = outc @ fcW^T + fcb  (M-fastest grid for fcW L2 reuse)
    gemm_tc_mfirst<<<dim3(T_LEN / 128, (LOC_N + 127) / 128), 256>>>(potb, pfcb, py, fcb,
                                                                    LOC_N, FC_K);
    // 10. log_softmax -> output
    logsoftmax_kernel<<<T_LEN, 512>>>(out);
}

// round 13
// speedup vs baseline: 1.5172x; 1.5172x over previous
#include <cuda_runtime.h>
#include <cuda_bf16.h>
#include <math.h>
#include <stdint.h>

#define S_LEN 5120
#define T_LEN 1024
#define SH_LEN 4096
#define H_DIM 512
#define D_DIM 608
#define G_DIM 2048
#define LOC_N 50000
#define FC_K 1088
#define DU_DIM 64
#define NB 64                 // fallback LSTM blocks per group
#define CL 16                 // cluster size for DSMEM LSTM
#define SENT_U 0x3FC00000u    // 1.5f fp32 sentinel (fallback path)
#define SENT32 0x3FC03FC0u    // bf16x2 {1.5,1.5} sentinel (cluster path)

// ---------------- scratch (device globals; no allocation allowed) ----------
__device__ float g_pre_enc[SH_LEN * G_DIM];
__device__ float g_pre_dec[T_LEN * G_DIM];
__device__ float g_hh[SH_LEN * H_DIM];     // fallback path only
__device__ float g_hd[T_LEN * H_DIM];      // fallback path only
__device__ float g_attn[(size_t)T_LEN * SH_LEN];
__device__ float g_ctx[T_LEN * H_DIM];
__device__ float g_y[(size_t)T_LEN * LOC_N];

// bf16 operand buffers
__device__ __nv_bfloat16 g_xb[S_LEN * D_DIM];
__device__ __nv_bfloat16 g_wihb_e[G_DIM * D_DIM];
__device__ __nv_bfloat16 g_wihb_d[G_DIM * D_DIM];
__device__ __nv_bfloat16 g_fcWb[(size_t)LOC_N * FC_K];
__device__ __nv_bfloat16 g_hhb[SH_LEN * H_DIM];
__device__ __nv_bfloat16 g_hdb[T_LEN * H_DIM];
__device__ __nv_bfloat16 g_hhTb[H_DIM * SH_LEN];
__device__ __nv_bfloat16 g_attnb[(size_t)T_LEN * SH_LEN];
__device__ __nv_bfloat16 g_outb[T_LEN * FC_K];

// ------- embedding gather -> bf16 directly (+ sentinel fill for fallback) --
__global__ void embed_kernel(const int* __restrict__ loc, const int* __restrict__ tim,
                             const int* __restrict__ clu,
                             const float* __restrict__ el, const float* __restrict__ et,
                             const float* __restrict__ ec) {
    int s = blockIdx.x, t = threadIdx.x;
    __nv_bfloat16* xrow = &g_xb[(size_t)s * D_DIM];
    if (t < 128) {
        float4 sv = make_float4(1.5f, 1.5f, 1.5f, 1.5f);
        if (s < SH_LEN) *(float4*)&g_hh[(size_t)s * H_DIM + t * 4] = sv;
        if (s < T_LEN)  *(float4*)&g_hd[(size_t)s * H_DIM + t * 4] = sv;
        float4 v = *(const float4*)&el[(size_t)loc[s] * 512 + t * 4];
        __nv_bfloat162 o[2];
        o[0] = __float22bfloat162_rn(make_float2(v.x, v.y));
        o[1] = __float22bfloat162_rn(make_float2(v.z, v.w));
        *(uint2*)&xrow[t * 4] = *(uint2*)o;
    } else if (t < 136) {
        int j = t - 128;
        float4 v = *(const float4*)&et[(size_t)tim[s] * 32 + j * 4];
        __nv_bfloat162 o[2];
        o[0] = __float22bfloat162_rn(make_float2(v.x, v.y));
        o[1] = __float22bfloat162_rn(make_float2(v.z, v.w));
        *(uint2*)&xrow[512 + j * 4] = *(uint2*)o;
    } else if (t < 152) {
        int j = t - 136;
        float4 v = *(const float4*)&ec[(size_t)clu[s] * 64 + j * 4];
        __nv_bfloat162 o[2];
        o[0] = __float22bfloat162_rn(make_float2(v.x, v.y));
        o[1] = __float22bfloat162_rn(make_float2(v.z, v.w));
        *(uint2*)&xrow[544 + j * 4] = *(uint2*)o;
    }
}

// ---------------- fp32 -> bf16 conversions ----------------
__global__ void f2b16_kernel(const float* __restrict__ in, __nv_bfloat16* __restrict__ out,
                             int n) {
    int i = (blockIdx.x * blockDim.x + threadIdx.x) * 16;
    if (i < n) {
#pragma unroll
        for (int h = 0; h < 2; h++) {
            float4 v0 = *(const float4*)&in[i + h * 8];
            float4 v1 = *(const float4*)&in[i + h * 8 + 4];
            __nv_bfloat162 o[4];
            o[0] = __float22bfloat162_rn(make_float2(v0.x, v0.y));
            o[1] = __float22bfloat162_rn(make_float2(v0.z, v0.w));
            o[2] = __float22bfloat162_rn(make_float2(v1.x, v1.y));
            o[3] = __float22bfloat162_rn(make_float2(v1.z, v1.w));
            *(int4*)&out[i + h * 8] = *(int4*)o;
        }
    }
}

__global__ void f2bw_kernel(const float* __restrict__ e, const float* __restrict__ d) {
    int bid = blockIdx.x;
    const float* in;
    __nv_bfloat16* out;
    if (bid < 608) { in = e; out = g_wihb_e; }
    else { in = d; out = g_wihb_d; bid -= 608; }
    int i = (bid * 256 + threadIdx.x) * 8;
    float4 v0 = *(const float4*)&in[i];
    float4 v1 = *(const float4*)&in[i + 4];
    __nv_bfloat162 o[4];
    o[0] = __float22bfloat162_rn(make_float2(v0.x, v0.y));
    o[1] = __float22bfloat162_rn(make_float2(v0.z, v0.w));
    o[2] = __float22bfloat162_rn(make_float2(v1.x, v1.y));
    o[3] = __float22bfloat162_rn(make_float2(v1.z, v1.w));
    *(int4*)&out[i] = *(int4*)o;
}

// ---------------- bf16 tensor-core GEMM body: C = A @ B^T + bias ---------
__device__ __forceinline__ void ldsm4(uint32_t& r0, uint32_t& r1, uint32_t& r2,
                                      uint32_t& r3, uint32_t a) {
    asm volatile("ldmatrix.sync.aligned.m8n8.x4.shared.b16 {%0,%1,%2,%3}, [%4];"
                 : "=r"(r0), "=r"(r1), "=r"(r2), "=r"(r3) : "r"(a));
}
__device__ __forceinline__ void mma16816(float* c, const uint32_t* a, const uint32_t* b) {
    asm volatile(
        "mma.sync.aligned.m16n8k16.row.col.f32.bf16.bf16.f32 "
        "{%0,%1,%2,%3},{%4,%5,%6,%7},{%8,%9},{%0,%1,%2,%3};"
        : "+f"(c[0]), "+f"(c[1]), "+f"(c[2]), "+f"(c[3])
        : "r"(a[0]), "r"(a[1]), "r"(a[2]), "r"(a[3]), "r"(b[0]), "r"(b[1]));
}

__device__ __forceinline__ void gemm_body(
    const __nv_bfloat16* __restrict__ A, const __nv_bfloat16* __restrict__ B,
    float* __restrict__ C, const float* __restrict__ bias1,
    const float* __restrict__ bias2, int m0, int n0, int N, int K)
{
    __shared__ __nv_bfloat16 As[2][128][40];
    __shared__ __nv_bfloat16 Bs[2][128][40];
    const int tid = threadIdx.x, lane = tid & 31, warp = tid >> 5;
    const int wm = warp & 1, wn = warp >> 1;
    const int lr = tid >> 2;
    const int lc = (tid & 3) << 3;
    const int grp = lane >> 3, lrr = lane & 7;

    float acc[4][4][4];
#pragma unroll
    for (int i = 0; i < 4; i++)
#pragma unroll
        for (int j = 0; j < 4; j++)
#pragma unroll
            for (int r = 0; r < 4; r++) acc[i][j][r] = 0.f;

    int4 ra0, ra1, rb0, rb1;
    const int KT = K >> 5;
    const int4 zero4 = make_int4(0, 0, 0, 0);

    {
        const __nv_bfloat16* Ap = A + (size_t)(m0 + lr) * K + lc;
        ra0 = *(const int4*)Ap;
        ra1 = *(const int4*)(Ap + (size_t)64 * K);
        int nr0 = n0 + lr, nr1 = nr0 + 64;
        rb0 = (nr0 < N) ? *(const int4*)(B + (size_t)nr0 * K + lc) : zero4;
        rb1 = (nr1 < N) ? *(const int4*)(B + (size_t)nr1 * K + lc) : zero4;
    }
    *(int4*)&As[0][lr][lc] = ra0;
    *(int4*)&As[0][lr + 64][lc] = ra1;
    *(int4*)&Bs[0][lr][lc] = rb0;
    *(int4*)&Bs[0][lr + 64][lc] = rb1;
    __syncthreads();

    for (int kt = 0; kt < KT; kt++) {
        const int buf = kt & 1;
        if (kt + 1 < KT) {
            const int k0 = (kt + 1) << 5;
            const __nv_bfloat16* Ap = A + (size_t)(m0 + lr) * K + k0 + lc;
            ra0 = *(const int4*)Ap;
            ra1 = *(const int4*)(Ap + (size_t)64 * K);
            int nr0 = n0 + lr, nr1 = nr0 + 64;
            rb0 = (nr0 < N) ? *(const int4*)(B + (size_t)nr0 * K + k0 + lc) : zero4;
            rb1 = (nr1 < N) ? *(const int4*)(B + (size_t)nr1 * K + k0 + lc) : zero4;
        }
#pragma unroll
        for (int kk = 0; kk < 2; kk++) {
            const int kb = kk << 4;
            uint32_t af[4][4], bf[4][2];
#pragma unroll
            for (int mt = 0; mt < 4; mt++) {
                int row = wm * 64 + mt * 16 + ((grp & 1) << 3) + lrr;
                int col = kb + ((grp >> 1) << 3);
                ldsm4(af[mt][0], af[mt][1], af[mt][2], af[mt][3],
                      (uint32_t)__cvta_generic_to_shared(&As[buf][row][col]));
            }
#pragma unroll
            for (int nt2 = 0; nt2 < 2; nt2++) {
                int row = wn * 32 + nt2 * 16 + ((grp >> 1) << 3) + lrr;
                int col = kb + ((grp & 1) << 3);
                uint32_t r0, r1, r2, r3;
                ldsm4(r0, r1, r2, r3,
                      (uint32_t)__cvta_generic_to_shared(&Bs[buf][row][col]));
                bf[nt2 * 2][0] = r0; bf[nt2 * 2][1] = r1;
                bf[nt2 * 2 + 1][0] = r2; bf[nt2 * 2 + 1][1] = r3;
            }
#pragma unroll
            for (int mt = 0; mt < 4; mt++)
#pragma unroll
                for (int nt = 0; nt < 4; nt++)
                    mma16816(acc[mt][nt], af[mt], bf[nt]);
        }
        if (kt + 1 < KT) {
            const int nb = buf ^ 1;
            *(int4*)&As[nb][lr][lc] = ra0;
            *(int4*)&As[nb][lr + 64][lc] = ra1;
            *(int4*)&Bs[nb][lr][lc] = rb0;
            *(int4*)&Bs[nb][lr + 64][lc] = rb1;
            __syncthreads();
        }
    }

#pragma unroll
    for (int nt = 0; nt < 4; nt++) {
        int col = n0 + wn * 32 + nt * 8 + ((lane & 3) << 1);
        if (col >= N) continue;
        float b0 = 0.f, b1 = 0.f;
        if (bias1) { b0 += bias1[col]; b1 += bias1[col + 1]; }
        if (bias2) { b0 += bias2[col]; b1 += bias2[col + 1]; }
#pragma unroll
        for (int mt = 0; mt < 4; mt++) {
            int row = m0 + wm * 64 + mt * 16 + (lane >> 2);
            float2 v0 = make_float2(acc[mt][nt][0] + b0, acc[mt][nt][1] + b1);
            float2 v1 = make_float2(acc[mt][nt][2] + b0, acc[mt][nt][3] + b1);
            *(float2*)&C[(size_t)row * N + col] = v0;
            *(float2*)&C[(size_t)(row + 8) * N + col] = v1;
        }
    }
}

__global__ void __launch_bounds__(256) gemm_tc(
    const __nv_bfloat16* __restrict__ A, const __nv_bfloat16* __restrict__ B,
    float* __restrict__ C, const float* __restrict__ bias1,
    const float* __restrict__ bias2, int N, int K)
{
    gemm_body(A, B, C, bias1, bias2, blockIdx.y * 128, blockIdx.x * 128, N, K);
}

__global__ void __launch_bounds__(256) gemm_pre(
    float* __restrict__ Ce, float* __restrict__ Cd,
    const float* __restrict__ ebih, const float* __restrict__ ebhh,
    const float* __restrict__ dbih, const float* __restrict__ dbhh)
{
    int by = blockIdx.y;
    if (by < 32)
        gemm_body(g_xb, g_wihb_e, Ce, ebih, ebhh, by * 128, blockIdx.x * 128,
                  G_DIM, D_DIM);
    else
        gemm_body(g_xb + (size_t)SH_LEN * D_DIM, g_wihb_d, Cd, dbih, dbhh,
                  (by - 32) * 128, blockIdx.x * 128, G_DIM, D_DIM);
}

// ---------------- LSTM helpers ----------------
__device__ __forceinline__ float tanhap(float x) {
    float y; asm("tanh.approx.f32 %0, %1;" : "=f"(y) : "f"(x)); return y;
}
__device__ __forceinline__ float sigap(float x) {
    return 0.5f * tanhap(0.5f * x) + 0.5f;
}
__device__ __forceinline__ void ffma2(uint64_t& acc, uint64_t a, uint64_t b) {
    asm("fma.rn.f32x2 %0, %1, %2, %0;" : "+l"(acc) : "l"(a), "l"(b));
}
__device__ __forceinline__ uint32_t packbf(float2 v) {
    __nv_bfloat162 b = __float22bfloat162_rn(v);
    return *(uint32_t*)&b;
}

// ============ cluster DSMEM LSTM (proven R9 version, byte-identical) =======
// CTA rank r owns units [32r, 32r+32) = 128 gate rows. Warp w: local rows
// [16w,16w+16); A-fragments in registers. warp0 does gates+publish while
// warps 1-7 race ahead. 4-slot sentinel ring -> reset folds behind S1
// (2 block barriers per step). Publish: 32 lanes x 8 remote stores.
__global__ void __launch_bounds__(256, 1) lstm_cluster_kernel(
    const float* __restrict__ preE, const float* __restrict__ WhhE,
    const float* __restrict__ preD, const float* __restrict__ WhhD)
{
    __shared__ __align__(16) unsigned int hbuf[4][256];   // 512 bf16 units/slot
    __shared__ float gsm[128];

    const int tid = threadIdx.x, lane = tid & 31, warp = tid >> 5;
    uint32_t rank;
    asm("mov.u32 %0, %%cluster_ctarank;" : "=r"(rank));
    const bool enc = (blockIdx.x >> 4) == 0;
    const float* pre = enc ? preE : preD;
    const float* Whh = enc ? WhhE : WhhD;
    __nv_bfloat16* hb = enc ? g_hhb : g_hdb;
    const int T = enc ? SH_LEN : T_LEN;

    // init all 4 sentinel slots
#pragma unroll
    for (int s = 0; s < 4; s++) hbuf[s][tid] = SENT32;

    // load A fragments: 32 k-chunks x 4 regs (m16n8k16 A layout, bf16)
    uint32_t aW[32][4];
    {
        int i0 = lane >> 2;
        int r0 = 16 * warp + i0, r1 = r0 + 8;
        const float* W0 = Whh + (size_t)((r0 >> 5) * H_DIM + rank * 32 + (r0 & 31)) * H_DIM;
        const float* W1 = Whh + (size_t)((r1 >> 5) * H_DIM + rank * 32 + (r1 & 31)) * H_DIM;
        int kb = (lane & 3) * 2;
#pragma unroll
        for (int kc = 0; kc < 32; kc++) {
            int k = kc * 16 + kb;
            aW[kc][0] = packbf(*(const float2*)&W0[k]);
            aW[kc][1] = packbf(*(const float2*)&W1[k]);
            aW[kc][2] = packbf(*(const float2*)&W0[k + 8]);
            aW[kc][3] = packbf(*(const float2*)&W1[k + 8]);
        }
    }

    // cluster barrier: all smem sentinel-initialized before any remote store
    asm volatile("barrier.cluster.arrive.aligned;" ::: "memory");
    asm volatile("barrier.cluster.wait.aligned;" ::: "memory");

    float creg = 0.f;
    float pv0 = 0.f, pv1 = 0.f, pv2 = 0.f, pv3 = 0.f;
    if (warp == 0) {
        int u = rank * 32 + lane;
        pv0 = __ldg(&pre[0 * H_DIM + u]);
        pv1 = __ldg(&pre[1 * H_DIM + u]);
        pv2 = __ldg(&pre[2 * H_DIM + u]);
        pv3 = __ldg(&pre[3 * H_DIM + u]);
    }

    for (int t = 0; t < T; t++) {
        const int sl = t & 3, sp = (t - 1) & 3;

        if (t > 0) {    // wait for h(t-1): every thread polls its own word
            volatile unsigned int* hv = &hbuf[sp][tid];
            while (*hv == SENT32) { }
        }
        __syncthreads();   // S1: slot sp fully delivered, visible block-wide

        // reset slot consumed at step t-1 (safe: next write is h(t+2),
        // causally gated by our h(t+1) publish which follows this reset)
        if (t > 1) hbuf[(t - 2) & 3][tid] = SENT32;

        float v0 = 0.f, v1 = 0.f;
        if (t > 0) {
            float c[4][4];
#pragma unroll
            for (int g = 0; g < 4; g++)
#pragma unroll
                for (int j = 0; j < 4; j++) c[g][j] = 0.f;
#pragma unroll
            for (int kc = 0; kc < 32; kc++) {
                uint32_t b[2];
                b[0] = hbuf[sp][kc * 8 + (lane & 3)];
                b[1] = hbuf[sp][kc * 8 + 4 + (lane & 3)];
                mma16816(c[kc >> 3], aW[kc], b);
            }
            v0 = c[0][0] + c[1][0] + c[2][0] + c[3][0];
            v1 = c[0][2] + c[1][2] + c[2][2] + c[3][2];
        }
        if ((lane & 3) == 0) {
            gsm[16 * warp + (lane >> 2)] = v0;
            gsm[16 * warp + 8 + (lane >> 2)] = v1;
        }
        __syncthreads();   // S3: gsm ready

        if (warp == 0) {
            float ig = sigap(gsm[lane] + pv0);
            float fg = sigap(gsm[32 + lane] + pv1);
            float gg = tanhap(gsm[64 + lane] + pv2);
            float og = sigap(gsm[96 + lane] + pv3);
            float cc = fg * creg + ig * gg;
            creg = cc;
            float h = og * tanhap(cc);
            __nv_bfloat16 hbf = __float2bfloat16(h);
            unsigned int mine = *(unsigned short*)&hbf;
            unsigned int nbv = __shfl_down_sync(0xffffffffu, mine, 1);
            unsigned int word = mine | (nbv << 16);           // valid on even lanes
            unsigned int wAll = __shfl_sync(0xffffffffu, word, lane & 30);
            if (t + 1 < T) {
                // 32 lanes x 8 ranks: lane pair (2k,2k+1) shares word k
                int rbase = (lane & 1) * 8;
                uint32_t laddr = (uint32_t)__cvta_generic_to_shared(
                    &hbuf[sl][rank * 16 + (lane >> 1)]);
#pragma unroll
                for (int pr = 0; pr < 8; pr++) {
                    uint32_t pa;
                    asm("mapa.shared::cluster.u32 %0, %1, %2;"
                        : "=r"(pa) : "r"(laddr), "r"(rbase + pr));
                    asm volatile("st.shared::cluster.u32 [%0], %1;"
                                 :: "r"(pa), "r"(wAll) : "memory");
                }
            }
            // side outputs (off critical path)
            int gu = rank * 32 + lane;
            hb[(size_t)t * H_DIM + gu] = hbf;
            if (enc) g_hhTb[(size_t)gu * SH_LEN + t] = hbf;
            if (t + 1 < T) {
                const float* pn = pre + (size_t)(t + 1) * G_DIM + gu;
                pv0 = __ldg(&pn[0 * H_DIM]);
                pv1 = __ldg(&pn[1 * H_DIM]);
                pv2 = __ldg(&pn[2 * H_DIM]);
                pv3 = __ldg(&pn[3 * H_DIM]);
            }
        }
    }

    asm volatile("barrier.cluster.arrive.aligned;" ::: "memory");
    asm volatile("barrier.cluster.wait.aligned;" ::: "memory");
}

// ============ fallback: L2 sentinel LSTM (R6 design, proven) ==============
__global__ void __launch_bounds__(256) lstm_fused_kernel(
    const float* __restrict__ preE, const float* __restrict__ WhhE, float* __restrict__ histE,
    const float* __restrict__ preD, const float* __restrict__ WhhD, float* __restrict__ histD)
{
    __shared__ __align__(16) float hs[H_DIM];
    __shared__ float gs[32];
    __shared__ float ps[32];

    const bool enc = blockIdx.x < NB;
    const float* pre  = enc ? preE : preD;
    const float* Whh  = enc ? WhhE : WhhD;
    float* hist       = enc ? histE : histD;
    __nv_bfloat16* hb = enc ? g_hhb : g_hdb;
    const int T       = enc ? SH_LEN : T_LEN;

    const int b = enc ? blockIdx.x : blockIdx.x - NB;
    const int tid = threadIdx.x, lane = tid & 31, warp = tid >> 5;

    uint64_t w2[4][8];
#pragma unroll
    for (int rr = 0; rr < 4; rr++) {
        int r = warp * 4 + rr, g = r >> 3, u = r & 7;
        int grow = g * H_DIM + b * 8 + u;
        const ulonglong2* src = (const ulonglong2*)&Whh[(size_t)grow * H_DIM + lane * 16];
#pragma unroll
        for (int j = 0; j < 4; j++) {
            ulonglong2 v = src[j];
            w2[rr][2 * j] = v.x; w2[rr][2 * j + 1] = v.y;
        }
    }
    float creg = 0.f;

    float psv = 0.f;
    if (tid < 32)
        psv = __ldg(&pre[(tid >> 3) * H_DIM + b * 8 + (tid & 7)]);

    for (int t = 0; t < T; t++) {
        if (t == 0) {
            hs[2 * tid] = 0.f; hs[2 * tid + 1] = 0.f;
        } else {
            const float* src = &hist[(size_t)(t - 1) * H_DIM + 2 * tid];
            float hx, hy;
            unsigned int ux, uy;
            do {
                asm volatile("ld.volatile.global.v2.f32 {%0,%1}, [%2];"
                             : "=f"(hx), "=f"(hy) : "l"(src) : "memory");
                ux = __float_as_uint(hx); uy = __float_as_uint(hy);
            } while (ux == SENT_U || uy == SENT_U);
            hs[2 * tid] = hx; hs[2 * tid + 1] = hy;
        }
        if (tid < 32) ps[tid] = psv;
        __syncthreads();

        if (tid < 32 && t + 1 < T)
            psv = __ldg(&pre[(size_t)(t + 1) * G_DIM + (tid >> 3) * H_DIM + b * 8 + (tid & 7)]);

        uint64_t acc2[4] = {0ull, 0ull, 0ull, 0ull};
        const uint64_t* h2p = (const uint64_t*)&hs[lane * 16];
#pragma unroll
        for (int j = 0; j < 8; j++) {
            uint64_t h2 = h2p[j];
#pragma unroll
            for (int rr = 0; rr < 4; rr++) ffma2(acc2[rr], w2[rr][j], h2);
        }
        float acc[4];
#pragma unroll
        for (int rr = 0; rr < 4; rr++) {
            union { uint64_t u; float2 f; } c; c.u = acc2[rr];
            acc[rr] = c.f.x + c.f.y;
        }
#pragma unroll
        for (int o = 16; o > 0; o >>= 1) {
#pragma unroll
            for (int rr = 0; rr < 4; rr++)
                acc[rr] += __shfl_xor_sync(0xffffffffu, acc[rr], o);
        }
        if (lane == 0) {
#pragma unroll
            for (int rr = 0; rr < 4; rr++)
                gs[warp * 4 + rr] = acc[rr] + ps[warp * 4 + rr];
        }
        __syncthreads();

        if (warp == 0 && lane < 8) {
            float ig = sigap(gs[lane]);
            float fg = sigap(gs[8 + lane]);
            float gg = tanhap(gs[16 + lane]);
            float og = sigap(gs[24 + lane]);
            float c = fg * creg + ig * gg;
            creg = c;
            float h = og * tanhap(c);
            int gu = b * 8 + lane;
            __stcg(&hist[(size_t)t * H_DIM + gu], h);
            hb[(size_t)t * H_DIM + gu] = __float2bfloat16(h);
            if (enc) g_hhTb[(size_t)gu * SH_LEN + t] = __float2bfloat16(h);
        }
    }
}

// ---------------- reductions ----------------
__device__ __forceinline__ float block_max_256(float v, float* red) {
#pragma unroll
    for (int o = 16; o > 0; o >>= 1) v = fmaxf(v, __shfl_xor_sync(0xffffffffu, v, o));
    if ((threadIdx.x & 31) == 0) red[threadIdx.x >> 5] = v;
    __syncthreads();
    if (threadIdx.x < 32) {
        float x = (threadIdx.x < 8) ? red[threadIdx.x] : -1e30f;
#pragma unroll
        for (int o = 4; o > 0; o >>= 1) x = fmaxf(x, __shfl_xor_sync(0xffffffffu, x, o));
        if (threadIdx.x == 0) red[0] = x;
    }
    __syncthreads();
    float r = red[0];
    __syncthreads();
    return r;
}

__device__ __forceinline__ float block_sum_256(float v, float* red) {
#pragma unroll
    for (int o = 16; o > 0; o >>= 1) v += __shfl_xor_sync(0xffffffffu, v, o);
    if ((threadIdx.x & 31) == 0) red[threadIdx.x >> 5] = v;
    __syncthreads();
    if (threadIdx.x < 32) {
        float x = (threadIdx.x < 8) ? red[threadIdx.x] : 0.f;
#pragma unroll
        for (int o = 4; o > 0; o >>= 1) x += __shfl_xor_sync(0xffffffffu, x, o);
        if (threadIdx.x == 0) red[0] = x;
    }
    __syncthreads();
    float r = red[0];
    __syncthreads();
    return r;
}

// softmax over rows of g_attn -> bf16 g_attnb
__global__ void __launch_bounds__(256) softmax_kernel() {
    __shared__ float red[8];
    const int row = blockIdx.x, tid = threadIdx.x;
    const float* X = &g_attn[(size_t)row * SH_LEN];
    __nv_bfloat16* O = &g_attnb[(size_t)row * SH_LEN];
    float v[16];
    float m = -1e30f;
#pragma unroll
    for (int j = 0; j < 16; j++) { v[j] = X[tid + j * 256]; m = fmaxf(m, v[j]); }
    m = block_max_256(m, red);
    float s = 0.f;
#pragma unroll
    for (int j = 0; j < 16; j++) { v[j] = expf(v[j] - m); s += v[j]; }
    s = block_sum_256(s, red);
    float inv = 1.f / s;
#pragma unroll
    for (int j = 0; j < 16; j++) O[tid + j * 256] = __float2bfloat16(v[j] * inv);
}

// log_softmax over rows of g_y -> out (online, 512 thr)
__global__ void __launch_bounds__(512) logsoftmax_kernel(float* __restrict__ out) {
    __shared__ float redm[16], reds[16];
    const int row = blockIdx.x, tid = threadIdx.x;
    const int lane = tid & 31, warp = tid >> 5;
    const float* Y = &g_y[(size_t)row * LOC_N];
    float* O = &out[(size_t)row * LOC_N];

    float m = -1e30f, s = 0.f;
    for (int c = tid * 4; c < LOC_N; c += 2048) {
        float4 v = *(const float4*)&Y[c];
        float ml = fmaxf(fmaxf(v.x, v.y), fmaxf(v.z, v.w));
        if (ml > m) { s *= __expf(m - ml); m = ml; }
        s += __expf(v.x - m) + __expf(v.y - m) + __expf(v.z - m) + __expf(v.w - m);
    }
#pragma unroll
    for (int o = 16; o > 0; o >>= 1) {
        float m2 = __shfl_xor_sync(0xffffffffu, m, o);
        float s2 = __shfl_xor_sync(0xffffffffu, s, o);
        float M = fmaxf(m, m2);
        s = s * __expf(m - M) + s2 * __expf(m2 - M);
        m = M;
    }
    if (lane == 0) { redm[warp] = m; reds[warp] = s; }
    __syncthreads();
    if (tid < 32) {
        float mm = (tid < 16) ? redm[tid] : -1e30f;
        float ss = (tid < 16) ? reds[tid] : 0.f;
#pragma unroll
        for (int o = 8; o > 0; o >>= 1) {
            float m2 = __shfl_xor_sync(0xffffffffu, mm, o);
            float s2 = __shfl_xor_sync(0xffffffffu, ss, o);
            float M = fmaxf(mm, m2);
            ss = ss * __expf(mm - M) + s2 * __expf(m2 - M);
            mm = M;
        }
        if (tid == 0) { redm[0] = mm; reds[0] = ss; }
    }
    __syncthreads();
    float ls = redm[0] + logf(reds[0]);
    for (int c = tid * 4; c < LOC_N; c += 2048) {
        float4 v = *(const float4*)&Y[c];
        v.x -= ls; v.y -= ls; v.z -= ls; v.w -= ls;
        *(float4*)&O[c] = v;
    }
}

// concat [hd(bf16) | ctx | uid_emb] -> g_outb bf16 [T_LEN, FC_K]
__global__ void concat_kernel(const float* __restrict__ emb_uid, const int* __restrict__ uid) {
    int row = blockIdx.x, t = threadIdx.x;
    if (t < 128) {
        uint2 v = *(const uint2*)&g_hdb[(size_t)row * H_DIM + t * 4];
        *(uint2*)&g_outb[(size_t)row * FC_K + t * 4] = v;
    } else {
        float4 v;
        if (t < 256) v = *(const float4*)&g_ctx[(size_t)row * H_DIM + (t - 128) * 4];
        else         v = *(const float4*)&emb_uid[(size_t)uid[0] * DU_DIM + (t - 256) * 4];
        __nv_bfloat162 o[2];
        o[0] = __float22bfloat162_rn(make_float2(v.x, v.y));
        o[1] = __float22bfloat162_rn(make_float2(v.z, v.w));
        *(uint2*)&g_outb[(size_t)row * FC_K + t * 4] = *(uint2*)o;
    }
}

// ---------------- host ----------------
extern "C" void kernel_launch(void* const* d_in, const int* in_sizes, int n_in,
                              void* d_out, int out_size) {
    const int* loc = (const int*)d_in[0];
    const int* tim = (const int*)d_in[1];
    const int* clu = (const int*)d_in[2];
    const int* uid = (const int*)d_in[3];
    const float* emb_loc = (const float*)d_in[5];
    const float* emb_tim = (const float*)d_in[6];
    const float* emb_clu = (const float*)d_in[7];
    const float* emb_uid = (const float*)d_in[8];
    const float* eWih = (const float*)d_in[9];
    const float* eWhh = (const float*)d_in[10];
    const float* ebih = (const float*)d_in[11];
    const float* ebhh = (const float*)d_in[12];
    const float* dWih = (const float*)d_in[13];
    const float* dWhh = (const float*)d_in[14];
    const float* dbih = (const float*)d_in[15];
    const float* dbhh = (const float*)d_in[16];
    const float* fcW = (const float*)d_in[17];
    const float* fcb = (const float*)d_in[18];
    float* out = (float*)d_out;

    float *ppe, *ppd, *phh, *phd, *pat, *pcx, *py;
    cudaGetSymbolAddress((void**)&ppe, g_pre_enc);
    cudaGetSymbolAddress((void**)&ppd, g_pre_dec);
    cudaGetSymbolAddress((void**)&phh, g_hh);
    cudaGetSymbolAddress((void**)&phd, g_hd);
    cudaGetSymbolAddress((void**)&pat, g_attn);
    cudaGetSymbolAddress((void**)&pcx, g_ctx);
    cudaGetSymbolAddress((void**)&py,  g_y);
    __nv_bfloat16 *pfcb, *phhb, *phdb, *phhTb, *patb, *potb;
    cudaGetSymbolAddress((void**)&pfcb,  g_fcWb);
    cudaGetSymbolAddress((void**)&phhb,  g_hhb);
    cudaGetSymbolAddress((void**)&phdb,  g_hdb);
    cudaGetSymbolAddress((void**)&phhTb, g_hhTb);
    cudaGetSymbolAddress((void**)&patb,  g_attnb);
    cudaGetSymbolAddress((void**)&potb,  g_outb);

    // 0. embed -> bf16 x; sentinel fill (for fallback path)
    embed_kernel<<<S_LEN, 152>>>(loc, tim, clu, emb_loc, emb_tim, emb_clu);
    // 1. Wih conversions
    f2bw_kernel<<<1216, 256>>>(eWih, dWih);
    // 2. both input projections
    gemm_pre<<<dim3(G_DIM / 128, 40), 256>>>(ppe, ppd, ebih, ebhh, dbih, dbhh);

    // 3. LSTMs: cluster-DSMEM path if 16-CTA clusters supported, else L2 path
    cudaLaunchAttribute cattr[1];
    cattr[0].id = cudaLaunchAttributeClusterDimension;
    cattr[0].val.clusterDim.x = CL; cattr[0].val.clusterDim.y = 1;
    cattr[0].val.clusterDim.z = 1;
    cudaLaunchConfig_t cfg = {};
    cfg.gridDim = dim3(2 * CL, 1, 1);
    cfg.blockDim = dim3(256, 1, 1);
    cfg.dynamicSmemBytes = 0;
    cfg.stream = 0;
    cfg.attrs = cattr;
    cfg.numAttrs = 1;
    cudaError_t ra = cudaFuncSetAttribute(
        lstm_cluster_kernel, cudaFuncAttributeNonPortableClusterSizeAllowed, 1);
    int ncl = 0;
    cudaError_t rb = cudaOccupancyMaxActiveClusters(&ncl, lstm_cluster_kernel, &cfg);
    (void)cudaGetLastError();
    if (ra == cudaSuccess && rb == cudaSuccess && ncl >= 2) {
        cudaLaunchKernelEx(&cfg, lstm_cluster_kernel, (const float*)ppe, eWhh,
                           (const float*)ppd, dWhh);
    } else {
        lstm_fused_kernel<<<2 * NB, 256>>>(ppe, eWhh, phh, ppd, dWhh, phd);
    }

    // 4. fcW conversion
    f2b16_kernel<<<(LOC_N * FC_K / 16 + 255) / 256, 256>>>(fcW, pfcb, LOC_N * FC_K);
    // 5. attention scores = hd @ hh^T
    gemm_tc<<<dim3(SH_LEN / 128, T_LEN / 128), 256>>>(phdb, phhb, pat, nullptr, nullptr,
                                                      SH_LEN, H_DIM);
    // 6. softmax rows -> bf16
    softmax_kernel<<<T_LEN, 256>>>();
    // 7. context = attn @ hh
    gemm_tc<<<dim3(H_DIM / 128, T_LEN / 128), 256>>>(patb, phhTb, pcx, nullptr, nullptr,
                                                     H_DIM, SH_LEN);
    // 8. concat -> bf16
    concat_kernel<<<T_LEN, 272>>>(emb_uid, uid);
    // 9. FC: y = outc @ fcW^T + fcb
    gemm_tc<<<dim3((LOC_N + 127) / 128, T_LEN / 128), 256>>>(potb, pfcb, py, fcb, nullptr,
                                                             LOC_N, FC_K);
    // 10. log_softmax -> output
    logsoftmax_kernel<<<T_LEN, 512>>>(out);
}

// round 14
// speedup vs baseline: 1.5189x; 1.0011x over previous
#include <cuda_runtime.h>
#include <cuda_bf16.h>
#include <math.h>
#include <stdint.h>

#define S_LEN 5120
#define T_LEN 1024
#define SH_LEN 4096
#define H_DIM 512
#define D_DIM 608
#define G_DIM 2048
#define LOC_N 50000
#define FC_K 1088
#define DU_DIM 64
#define NB 64                 // fallback LSTM blocks per group
#define CL 16                 // cluster size for DSMEM LSTM
#define SENT_U 0x3FC00000u    // 1.5f fp32 sentinel (fallback path)
#define SENT32 0x3FC03FC0u    // bf16x2 {1.5,1.5} sentinel (cluster path)

// ---------------- scratch (device globals; no allocation allowed) ----------
__device__ float g_pre_enc[SH_LEN * G_DIM];
__device__ float g_pre_dec[T_LEN * G_DIM];
__device__ float g_hh[SH_LEN * H_DIM];     // fallback path only
__device__ float g_hd[T_LEN * H_DIM];      // fallback path only
__device__ float g_attn[(size_t)T_LEN * SH_LEN];
__device__ float g_ctx[T_LEN * H_DIM];
__device__ float g_y[(size_t)T_LEN * LOC_N];

// bf16 operand buffers
__device__ __nv_bfloat16 g_xb[S_LEN * D_DIM];
__device__ __nv_bfloat16 g_wihb_e[G_DIM * D_DIM];
__device__ __nv_bfloat16 g_wihb_d[G_DIM * D_DIM];
__device__ __nv_bfloat16 g_fcWb[(size_t)LOC_N * FC_K];
__device__ __nv_bfloat16 g_hhb[SH_LEN * H_DIM];
__device__ __nv_bfloat16 g_hdb[T_LEN * H_DIM];
__device__ __nv_bfloat16 g_hhTb[H_DIM * SH_LEN];
__device__ __nv_bfloat16 g_attnb[(size_t)T_LEN * SH_LEN];
__device__ __nv_bfloat16 g_outb[T_LEN * FC_K];

// ------- embedding gather -> bf16 directly (+ sentinel fill for fallback) --
__global__ void embed_kernel(const int* __restrict__ loc, const int* __restrict__ tim,
                             const int* __restrict__ clu,
                             const float* __restrict__ el, const float* __restrict__ et,
                             const float* __restrict__ ec) {
    int s = blockIdx.x, t = threadIdx.x;
    __nv_bfloat16* xrow = &g_xb[(size_t)s * D_DIM];
    if (t < 128) {
        float4 sv = make_float4(1.5f, 1.5f, 1.5f, 1.5f);
        if (s < SH_LEN) *(float4*)&g_hh[(size_t)s * H_DIM + t * 4] = sv;
        if (s < T_LEN)  *(float4*)&g_hd[(size_t)s * H_DIM + t * 4] = sv;
        float4 v = *(const float4*)&el[(size_t)loc[s] * 512 + t * 4];
        __nv_bfloat162 o[2];
        o[0] = __float22bfloat162_rn(make_float2(v.x, v.y));
        o[1] = __float22bfloat162_rn(make_float2(v.z, v.w));
        *(uint2*)&xrow[t * 4] = *(uint2*)o;
    } else if (t < 136) {
        int j = t - 128;
        float4 v = *(const float4*)&et[(size_t)tim[s] * 32 + j * 4];
        __nv_bfloat162 o[2];
        o[0] = __float22bfloat162_rn(make_float2(v.x, v.y));
        o[1] = __float22bfloat162_rn(make_float2(v.z, v.w));
        *(uint2*)&xrow[512 + j * 4] = *(uint2*)o;
    } else if (t < 152) {
        int j = t - 136;
        float4 v = *(const float4*)&ec[(size_t)clu[s] * 64 + j * 4];
        __nv_bfloat162 o[2];
        o[0] = __float22bfloat162_rn(make_float2(v.x, v.y));
        o[1] = __float22bfloat162_rn(make_float2(v.z, v.w));
        *(uint2*)&xrow[544 + j * 4] = *(uint2*)o;
    }
}

// ---------------- fp32 -> bf16 conversions ----------------
__global__ void f2b16_kernel(const float* __restrict__ in, __nv_bfloat16* __restrict__ out,
                             int n) {
    int i = (blockIdx.x * blockDim.x + threadIdx.x) * 16;
    if (i < n) {
#pragma unroll
        for (int h = 0; h < 2; h++) {
            float4 v0 = *(const float4*)&in[i + h * 8];
            float4 v1 = *(const float4*)&in[i + h * 8 + 4];
            __nv_bfloat162 o[4];
            o[0] = __float22bfloat162_rn(make_float2(v0.x, v0.y));
            o[1] = __float22bfloat162_rn(make_float2(v0.z, v0.w));
            o[2] = __float22bfloat162_rn(make_float2(v1.x, v1.y));
            o[3] = __float22bfloat162_rn(make_float2(v1.z, v1.w));
            *(int4*)&out[i + h * 8] = *(int4*)o;
        }
    }
}

__global__ void f2bw_kernel(const float* __restrict__ e, const float* __restrict__ d) {
    int bid = blockIdx.x;
    const float* in;
    __nv_bfloat16* out;
    if (bid < 608) { in = e; out = g_wihb_e; }
    else { in = d; out = g_wihb_d; bid -= 608; }
    int i = (bid * 256 + threadIdx.x) * 8;
    float4 v0 = *(const float4*)&in[i];
    float4 v1 = *(const float4*)&in[i + 4];
    __nv_bfloat162 o[4];
    o[0] = __float22bfloat162_rn(make_float2(v0.x, v0.y));
    o[1] = __float22bfloat162_rn(make_float2(v0.z, v0.w));
    o[2] = __float22bfloat162_rn(make_float2(v1.x, v1.y));
    o[3] = __float22bfloat162_rn(make_float2(v1.z, v1.w));
    *(int4*)&out[i] = *(int4*)o;
}

// ---------------- bf16 tensor-core GEMM body: C = A @ B^T + bias ---------
__device__ __forceinline__ void ldsm4(uint32_t& r0, uint32_t& r1, uint32_t& r2,
                                      uint32_t& r3, uint32_t a) {
    asm volatile("ldmatrix.sync.aligned.m8n8.x4.shared.b16 {%0,%1,%2,%3}, [%4];"
                 : "=r"(r0), "=r"(r1), "=r"(r2), "=r"(r3) : "r"(a));
}
__device__ __forceinline__ void mma16816(float* c, const uint32_t* a, const uint32_t* b) {
    asm volatile(
        "mma.sync.aligned.m16n8k16.row.col.f32.bf16.bf16.f32 "
        "{%0,%1,%2,%3},{%4,%5,%6,%7},{%8,%9},{%0,%1,%2,%3};"
        : "+f"(c[0]), "+f"(c[1]), "+f"(c[2]), "+f"(c[3])
        : "r"(a[0]), "r"(a[1]), "r"(a[2]), "r"(a[3]), "r"(b[0]), "r"(b[1]));
}

__device__ __forceinline__ void gemm_body(
    const __nv_bfloat16* __restrict__ A, const __nv_bfloat16* __restrict__ B,
    float* __restrict__ C, const float* __restrict__ bias1,
    const float* __restrict__ bias2, int m0, int n0, int N, int K)
{
    __shared__ __nv_bfloat16 As[2][128][40];
    __shared__ __nv_bfloat16 Bs[2][128][40];
    const int tid = threadIdx.x, lane = tid & 31, warp = tid >> 5;
    const int wm = warp & 1, wn = warp >> 1;
    const int lr = tid >> 2;
    const int lc = (tid & 3) << 3;
    const int grp = lane >> 3, lrr = lane & 7;

    float acc[4][4][4];
#pragma unroll
    for (int i = 0; i < 4; i++)
#pragma unroll
        for (int j = 0; j < 4; j++)
#pragma unroll
            for (int r = 0; r < 4; r++) acc[i][j][r] = 0.f;

    int4 ra0, ra1, rb0, rb1;
    const int KT = K >> 5;
    const int4 zero4 = make_int4(0, 0, 0, 0);

    {
        const __nv_bfloat16* Ap = A + (size_t)(m0 + lr) * K + lc;
        ra0 = *(const int4*)Ap;
        ra1 = *(const int4*)(Ap + (size_t)64 * K);
        int nr0 = n0 + lr, nr1 = nr0 + 64;
        rb0 = (nr0 < N) ? *(const int4*)(B + (size_t)nr0 * K + lc) : zero4;
        rb1 = (nr1 < N) ? *(const int4*)(B + (size_t)nr1 * K + lc) : zero4;
    }
    *(int4*)&As[0][lr][lc] = ra0;
    *(int4*)&As[0][lr + 64][lc] = ra1;
    *(int4*)&Bs[0][lr][lc] = rb0;
    *(int4*)&Bs[0][lr + 64][lc] = rb1;
    __syncthreads();

    for (int kt = 0; kt < KT; kt++) {
        const int buf = kt & 1;
        if (kt + 1 < KT) {
            const int k0 = (kt + 1) << 5;
            const __nv_bfloat16* Ap = A + (size_t)(m0 + lr) * K + k0 + lc;
            ra0 = *(const int4*)Ap;
            ra1 = *(const int4*)(Ap + (size_t)64 * K);
            int nr0 = n0 + lr, nr1 = nr0 + 64;
            rb0 = (nr0 < N) ? *(const int4*)(B + (size_t)nr0 * K + k0 + lc) : zero4;
            rb1 = (nr1 < N) ? *(const int4*)(B + (size_t)nr1 * K + k0 + lc) : zero4;
        }
#pragma unroll
        for (int kk = 0; kk < 2; kk++) {
            const int kb = kk << 4;
            uint32_t af[4][4], bf[4][2];
#pragma unroll
            for (int mt = 0; mt < 4; mt++) {
                int row = wm * 64 + mt * 16 + ((grp & 1) << 3) + lrr;
                int col = kb + ((grp >> 1) << 3);
                ldsm4(af[mt][0], af[mt][1], af[mt][2], af[mt][3],
                      (uint32_t)__cvta_generic_to_shared(&As[buf][row][col]));
            }
#pragma unroll
            for (int nt2 = 0; nt2 < 2; nt2++) {
                int row = wn * 32 + nt2 * 16 + ((grp >> 1) << 3) + lrr;
                int col = kb + ((grp & 1) << 3);
                uint32_t r0, r1, r2, r3;
                ldsm4(r0, r1, r2, r3,
                      (uint32_t)__cvta_generic_to_shared(&Bs[buf][row][col]));
                bf[nt2 * 2][0] = r0; bf[nt2 * 2][1] = r1;
                bf[nt2 * 2 + 1][0] = r2; bf[nt2 * 2 + 1][1] = r3;
            }
#pragma unroll
            for (int mt = 0; mt < 4; mt++)
#pragma unroll
                for (int nt = 0; nt < 4; nt++)
                    mma16816(acc[mt][nt], af[mt], bf[nt]);
        }
        if (kt + 1 < KT) {
            const int nb = buf ^ 1;
            *(int4*)&As[nb][lr][lc] = ra0;
            *(int4*)&As[nb][lr + 64][lc] = ra1;
            *(int4*)&Bs[nb][lr][lc] = rb0;
            *(int4*)&Bs[nb][lr + 64][lc] = rb1;
            __syncthreads();
        }
    }

#pragma unroll
    for (int nt = 0; nt < 4; nt++) {
        int col = n0 + wn * 32 + nt * 8 + ((lane & 3) << 1);
        if (col >= N) continue;
        float b0 = 0.f, b1 = 0.f;
        if (bias1) { b0 += bias1[col]; b1 += bias1[col + 1]; }
        if (bias2) { b0 += bias2[col]; b1 += bias2[col + 1]; }
#pragma unroll
        for (int mt = 0; mt < 4; mt++) {
            int row = m0 + wm * 64 + mt * 16 + (lane >> 2);
            float2 v0 = make_float2(acc[mt][nt][0] + b0, acc[mt][nt][1] + b1);
            float2 v1 = make_float2(acc[mt][nt][2] + b0, acc[mt][nt][3] + b1);
            *(float2*)&C[(size_t)row * N + col] = v0;
            *(float2*)&C[(size_t)(row + 8) * N + col] = v1;
        }
    }
}

__global__ void __launch_bounds__(256) gemm_tc(
    const __nv_bfloat16* __restrict__ A, const __nv_bfloat16* __restrict__ B,
    float* __restrict__ C, const float* __restrict__ bias1,
    const float* __restrict__ bias2, int N, int K)
{
    gemm_body(A, B, C, bias1, bias2, blockIdx.y * 128, blockIdx.x * 128, N, K);
}

__global__ void __launch_bounds__(256) gemm_pre(
    float* __restrict__ Ce, float* __restrict__ Cd,
    const float* __restrict__ ebih, const float* __restrict__ ebhh,
    const float* __restrict__ dbih, const float* __restrict__ dbhh)
{
    int by = blockIdx.y;
    if (by < 32)
        gemm_body(g_xb, g_wihb_e, Ce, ebih, ebhh, by * 128, blockIdx.x * 128,
                  G_DIM, D_DIM);
    else
        gemm_body(g_xb + (size_t)SH_LEN * D_DIM, g_wihb_d, Cd, dbih, dbhh,
                  (by - 32) * 128, blockIdx.x * 128, G_DIM, D_DIM);
}

// ---------------- LSTM helpers ----------------
__device__ __forceinline__ float tanhap(float x) {
    float y; asm("tanh.approx.f32 %0, %1;" : "=f"(y) : "f"(x)); return y;
}
__device__ __forceinline__ float sigap(float x) {
    return 0.5f * tanhap(0.5f * x) + 0.5f;
}
__device__ __forceinline__ void ffma2(uint64_t& acc, uint64_t a, uint64_t b) {
    asm("fma.rn.f32x2 %0, %1, %2, %0;" : "+l"(acc) : "l"(a), "l"(b));
}
__device__ __forceinline__ uint32_t packbf(float2 v) {
    __nv_bfloat162 b = __float22bfloat162_rn(v);
    return *(uint32_t*)&b;
}

// ============ cluster DSMEM LSTM (R9 + accumulator interleave fix) =========
// Identical to the reproducible 3820us baseline except ONE token:
// the mma accumulator index is kc&3 (rotating, independent chains) instead of
// kc>>3 (8-deep RAW chains). The output v = sum of ALL 4 accumulators, so the
// result is algebraically identical (fp order shifts only).
__global__ void __launch_bounds__(256, 1) lstm_cluster_kernel(
    const float* __restrict__ preE, const float* __restrict__ WhhE,
    const float* __restrict__ preD, const float* __restrict__ WhhD)
{
    __shared__ __align__(16) unsigned int hbuf[4][256];   // 512 bf16 units/slot
    __shared__ float gsm[128];

    const int tid = threadIdx.x, lane = tid & 31, warp = tid >> 5;
    uint32_t rank;
    asm("mov.u32 %0, %%cluster_ctarank;" : "=r"(rank));
    const bool enc = (blockIdx.x >> 4) == 0;
    const float* pre = enc ? preE : preD;
    const float* Whh = enc ? WhhE : WhhD;
    __nv_bfloat16* hb = enc ? g_hhb : g_hdb;
    const int T = enc ? SH_LEN : T_LEN;

    // init all 4 sentinel slots
#pragma unroll
    for (int s = 0; s < 4; s++) hbuf[s][tid] = SENT32;

    // load A fragments: 32 k-chunks x 4 regs (m16n8k16 A layout, bf16)
    uint32_t aW[32][4];
    {
        int i0 = lane >> 2;
        int r0 = 16 * warp + i0, r1 = r0 + 8;
        const float* W0 = Whh + (size_t)((r0 >> 5) * H_DIM + rank * 32 + (r0 & 31)) * H_DIM;
        const float* W1 = Whh + (size_t)((r1 >> 5) * H_DIM + rank * 32 + (r1 & 31)) * H_DIM;
        int kb = (lane & 3) * 2;
#pragma unroll
        for (int kc = 0; kc < 32; kc++) {
            int k = kc * 16 + kb;
            aW[kc][0] = packbf(*(const float2*)&W0[k]);
            aW[kc][1] = packbf(*(const float2*)&W1[k]);
            aW[kc][2] = packbf(*(const float2*)&W0[k + 8]);
            aW[kc][3] = packbf(*(const float2*)&W1[k + 8]);
        }
    }

    // cluster barrier: all smem sentinel-initialized before any remote store
    asm volatile("barrier.cluster.arrive.aligned;" ::: "memory");
    asm volatile("barrier.cluster.wait.aligned;" ::: "memory");

    float creg = 0.f;
    float pv0 = 0.f, pv1 = 0.f, pv2 = 0.f, pv3 = 0.f;
    if (warp == 0) {
        int u = rank * 32 + lane;
        pv0 = __ldg(&pre[0 * H_DIM + u]);
        pv1 = __ldg(&pre[1 * H_DIM + u]);
        pv2 = __ldg(&pre[2 * H_DIM + u]);
        pv3 = __ldg(&pre[3 * H_DIM + u]);
    }

    for (int t = 0; t < T; t++) {
        const int sl = t & 3, sp = (t - 1) & 3;

        if (t > 0) {    // wait for h(t-1): every thread polls its own word
            volatile unsigned int* hv = &hbuf[sp][tid];
            while (*hv == SENT32) { }
        }
        __syncthreads();   // S1: slot sp fully delivered, visible block-wide

        // reset slot consumed at step t-1 (safe: next write is h(t+2),
        // causally gated by our h(t+1) publish which follows this reset)
        if (t > 1) hbuf[(t - 2) & 3][tid] = SENT32;

        float v0 = 0.f, v1 = 0.f;
        if (t > 0) {
            float c[4][4];
#pragma unroll
            for (int g = 0; g < 4; g++)
#pragma unroll
                for (int j = 0; j < 4; j++) c[g][j] = 0.f;
#pragma unroll
            for (int kc = 0; kc < 32; kc++) {
                uint32_t b[2];
                b[0] = hbuf[sp][kc * 8 + (lane & 3)];
                b[1] = hbuf[sp][kc * 8 + 4 + (lane & 3)];
                mma16816(c[kc & 3], aW[kc], b);   // rotating accumulators
            }
            v0 = c[0][0] + c[1][0] + c[2][0] + c[3][0];
            v1 = c[0][2] + c[1][2] + c[2][2] + c[3][2];
        }
        if ((lane & 3) == 0) {
            gsm[16 * warp + (lane >> 2)] = v0;
            gsm[16 * warp + 8 + (lane >> 2)] = v1;
        }
        __syncthreads();   // S3: gsm ready

        if (warp == 0) {
            float ig = sigap(gsm[lane] + pv0);
            float fg = sigap(gsm[32 + lane] + pv1);
            float gg = tanhap(gsm[64 + lane] + pv2);
            float og = sigap(gsm[96 + lane] + pv3);
            float cc = fg * creg + ig * gg;
            creg = cc;
            float h = og * tanhap(cc);
            __nv_bfloat16 hbf = __float2bfloat16(h);
            unsigned int mine = *(unsigned short*)&hbf;
            unsigned int nbv = __shfl_down_sync(0xffffffffu, mine, 1);
            unsigned int word = mine | (nbv << 16);           // valid on even lanes
            unsigned int wAll = __shfl_sync(0xffffffffu, word, lane & 30);
            if (t + 1 < T) {
                // 32 lanes x 8 ranks: lane pair (2k,2k+1) shares word k
                int rbase = (lane & 1) * 8;
                uint32_t laddr = (uint32_t)__cvta_generic_to_shared(
                    &hbuf[sl][rank * 16 + (lane >> 1)]);
#pragma unroll
                for (int pr = 0; pr < 8; pr++) {
                    uint32_t pa;
                    asm("mapa.shared::cluster.u32 %0, %1, %2;"
                        : "=r"(pa) : "r"(laddr), "r"(rbase + pr));
                    asm volatile("st.shared::cluster.u32 [%0], %1;"
                                 :: "r"(pa), "r"(wAll) : "memory");
                }
            }
            // side outputs (off critical path)
            int gu = rank * 32 + lane;
            hb[(size_t)t * H_DIM + gu] = hbf;
            if (enc) g_hhTb[(size_t)gu * SH_LEN + t] = hbf;
            if (t + 1 < T) {
                const float* pn = pre + (size_t)(t + 1) * G_DIM + gu;
                pv0 = __ldg(&pn[0 * H_DIM]);
                pv1 = __ldg(&pn[1 * H_DIM]);
                pv2 = __ldg(&pn[2 * H_DIM]);
                pv3 = __ldg(&pn[3 * H_DIM]);
            }
        }
    }

    asm volatile("barrier.cluster.arrive.aligned;" ::: "memory");
    asm volatile("barrier.cluster.wait.aligned;" ::: "memory");
}

// ============ fallback: L2 sentinel LSTM (R6 design, proven) ==============
__global__ void __launch_bounds__(256) lstm_fused_kernel(
    const float* __restrict__ preE, const float* __restrict__ WhhE, float* __restrict__ histE,
    const float* __restrict__ preD, const float* __restrict__ WhhD, float* __restrict__ histD)
{
    __shared__ __align__(16) float hs[H_DIM];
    __shared__ float gs[32];
    __shared__ float ps[32];

    const bool enc = blockIdx.x < NB;
    const float* pre  = enc ? preE : preD;
    const float* Whh  = enc ? WhhE : WhhD;
    float* hist       = enc ? histE : histD;
    __nv_bfloat16* hb = enc ? g_hhb : g_hdb;
    const int T       = enc ? SH_LEN : T_LEN;

    const int b = enc ? blockIdx.x : blockIdx.x - NB;
    const int tid = threadIdx.x, lane = tid & 31, warp = tid >> 5;

    uint64_t w2[4][8];
#pragma unroll
    for (int rr = 0; rr < 4; rr++) {
        int r = warp * 4 + rr, g = r >> 3, u = r & 7;
        int grow = g * H_DIM + b * 8 + u;
        const ulonglong2* src = (const ulonglong2*)&Whh[(size_t)grow * H_DIM + lane * 16];
#pragma unroll
        for (int j = 0; j < 4; j++) {
            ulonglong2 v = src[j];
            w2[rr][2 * j] = v.x; w2[rr][2 * j + 1] = v.y;
        }
    }
    float creg = 0.f;

    float psv = 0.f;
    if (tid < 32)
        psv = __ldg(&pre[(tid >> 3) * H_DIM + b * 8 + (tid & 7)]);

    for (int t = 0; t < T; t++) {
        if (t == 0) {
            hs[2 * tid] = 0.f; hs[2 * tid + 1] = 0.f;
        } else {
            const float* src = &hist[(size_t)(t - 1) * H_DIM + 2 * tid];
            float hx, hy;
            unsigned int ux, uy;
            do {
                asm volatile("ld.volatile.global.v2.f32 {%0,%1}, [%2];"
                             : "=f"(hx), "=f"(hy) : "l"(src) : "memory");
                ux = __float_as_uint(hx); uy = __float_as_uint(hy);
            } while (ux == SENT_U || uy == SENT_U);
            hs[2 * tid] = hx; hs[2 * tid + 1] = hy;
        }
        if (tid < 32) ps[tid] = psv;
        __syncthreads();

        if (tid < 32 && t + 1 < T)
            psv = __ldg(&pre[(size_t)(t + 1) * G_DIM + (tid >> 3) * H_DIM + b * 8 + (tid & 7)]);

        uint64_t acc2[4] = {0ull, 0ull, 0ull, 0ull};
        const uint64_t* h2p = (const uint64_t*)&hs[lane * 16];
#pragma unroll
        for (int j = 0; j < 8; j++) {
            uint64_t h2 = h2p[j];
#pragma unroll
            for (int rr = 0; rr < 4; rr++) ffma2(acc2[rr], w2[rr][j], h2);
        }
        float acc[4];
#pragma unroll
        for (int rr = 0; rr < 4; rr++) {
            union { uint64_t u; float2 f; } c; c.u = acc2[rr];
            acc[rr] = c.f.x + c.f.y;
        }
#pragma unroll
        for (int o = 16; o > 0; o >>= 1) {
#pragma unroll
            for (int rr = 0; rr < 4; rr++)
                acc[rr] += __shfl_xor_sync(0xffffffffu, acc[rr], o);
        }
        if (lane == 0) {
#pragma unroll
            for (int rr = 0; rr < 4; rr++)
                gs[warp * 4 + rr] = acc[rr] + ps[warp * 4 + rr];
        }
        __syncthreads();

        if (warp == 0 && lane < 8) {
            float ig = sigap(gs[lane]);
            float fg = sigap(gs[8 + lane]);
            float gg = tanhap(gs[16 + lane]);
            float og = sigap(gs[24 + lane]);
            float c = fg * creg + ig * gg;
            creg = c;
            float h = og * tanhap(c);
            int gu = b * 8 + lane;
            __stcg(&hist[(size_t)t * H_DIM + gu], h);
            hb[(size_t)t * H_DIM + gu] = __float2bfloat16(h);
            if (enc) g_hhTb[(size_t)gu * SH_LEN + t] = __float2bfloat16(h);
        }
    }
}

// ---------------- reductions ----------------
__device__ __forceinline__ float block_max_256(float v, float* red) {
#pragma unroll
    for (int o = 16; o > 0; o >>= 1) v = fmaxf(v, __shfl_xor_sync(0xffffffffu, v, o));
    if ((threadIdx.x & 31) == 0) red[threadIdx.x >> 5] = v;
    __syncthreads();
    if (threadIdx.x < 32) {
        float x = (threadIdx.x < 8) ? red[threadIdx.x] : -1e30f;
#pragma unroll
        for (int o = 4; o > 0; o >>= 1) x = fmaxf(x, __shfl_xor_sync(0xffffffffu, x, o));
        if (threadIdx.x == 0) red[0] = x;
    }
    __syncthreads();
    float r = red[0];
    __syncthreads();
    return r;
}

__device__ __forceinline__ float block_sum_256(float v, float* red) {
#pragma unroll
    for (int o = 16; o > 0; o >>= 1) v += __shfl_xor_sync(0xffffffffu, v, o);
    if ((threadIdx.x & 31) == 0) red[threadIdx.x >> 5] = v;
    __syncthreads();
    if (threadIdx.x < 32) {
        float x = (threadIdx.x < 8) ? red[threadIdx.x] : 0.f;
#pragma unroll
        for (int o = 4; o > 0; o >>= 1) x += __shfl_xor_sync(0xffffffffu, x, o);
        if (threadIdx.x == 0) red[0] = x;
    }
    __syncthreads();
    float r = red[0];
    __syncthreads();
    return r;
}

// softmax over rows of g_attn -> bf16 g_attnb
__global__ void __launch_bounds__(256) softmax_kernel() {
    __shared__ float red[8];
    const int row = blockIdx.x, tid = threadIdx.x;
    const float* X = &g_attn[(size_t)row * SH_LEN];
    __nv_bfloat16* O = &g_attnb[(size_t)row * SH_LEN];
    float v[16];
    float m = -1e30f;
#pragma unroll
    for (int j = 0; j < 16; j++) { v[j] = X[tid + j * 256]; m = fmaxf(m, v[j]); }
    m = block_max_256(m, red);
    float s = 0.f;
#pragma unroll
    for (int j = 0; j < 16; j++) { v[j] = expf(v[j] - m); s += v[j]; }
    s = block_sum_256(s, red);
    float inv = 1.f / s;
#pragma unroll
    for (int j = 0; j < 16; j++) O[tid + j * 256] = __float2bfloat16(v[j] * inv);
}

// log_softmax over rows of g_y -> out (online, 512 thr)
__global__ void __launch_bounds__(512) logsoftmax_kernel(float* __restrict__ out) {
    __shared__ float redm[16], reds[16];
    const int row = blockIdx.x, tid = threadIdx.x;
    const int lane = tid & 31, warp = tid >> 5;
    const float* Y = &g_y[(size_t)row * LOC_N];
    float* O = &out[(size_t)row * LOC_N];

    float m = -1e30f, s = 0.f;
    for (int c = tid * 4; c < LOC_N; c += 2048) {
        float4 v = *(const float4*)&Y[c];
        float ml = fmaxf(fmaxf(v.x, v.y), fmaxf(v.z, v.w));
        if (ml > m) { s *= __expf(m - ml); m = ml; }
        s += __expf(v.x - m) + __expf(v.y - m) + __expf(v.z - m) + __expf(v.w - m);
    }
#pragma unroll
    for (int o = 16; o > 0; o >>= 1) {
        float m2 = __shfl_xor_sync(0xffffffffu, m, o);
        float s2 = __shfl_xor_sync(0xffffffffu, s, o);
        float M = fmaxf(m, m2);
        s = s * __expf(m - M) + s2 * __expf(m2 - M);
        m = M;
    }
    if (lane == 0) { redm[warp] = m; reds[warp] = s; }
    __syncthreads();
    if (tid < 32) {
        float mm = (tid < 16) ? redm[tid] : -1e30f;
        float ss = (tid < 16) ? reds[tid] : 0.f;
#pragma unroll
        for (int o = 8; o > 0; o >>= 1) {
            float m2 = __shfl_xor_sync(0xffffffffu, mm, o);
            float s2 = __shfl_xor_sync(0xffffffffu, ss, o);
            float M = fmaxf(mm, m2);
            ss = ss * __expf(mm - M) + s2 * __expf(m2 - M);
            mm = M;
        }
        if (tid == 0) { redm[0] = mm; reds[0] = ss; }
    }
    __syncthreads();
    float ls = redm[0] + logf(reds[0]);
    for (int c = tid * 4; c < LOC_N; c += 2048) {
        float4 v = *(const float4*)&Y[c];
        v.x -= ls; v.y -= ls; v.z -= ls; v.w -= ls;
        *(float4*)&O[c] = v;
    }
}

// concat [hd(bf16) | ctx | uid_emb] -> g_outb bf16 [T_LEN, FC_K]
__global__ void concat_kernel(const float* __restrict__ emb_uid, const int* __restrict__ uid) {
    int row = blockIdx.x, t = threadIdx.x;
    if (t < 128) {
        uint2 v = *(const uint2*)&g_hdb[(size_t)row * H_DIM + t * 4];
        *(uint2*)&g_outb[(size_t)row * FC_K + t * 4] = v;
    } else {
        float4 v;
        if (t < 256) v = *(const float4*)&g_ctx[(size_t)row * H_DIM + (t - 128) * 4];
        else         v = *(const float4*)&emb_uid[(size_t)uid[0] * DU_DIM + (t - 256) * 4];
        __nv_bfloat162 o[2];
        o[0] = __float22bfloat162_rn(make_float2(v.x, v.y));
        o[1] = __float22bfloat162_rn(make_float2(v.z, v.w));
        *(uint2*)&g_outb[(size_t)row * FC_K + t * 4] = *(uint2*)o;
    }
}

// ---------------- host ----------------
extern "C" void kernel_launch(void* const* d_in, const int* in_sizes, int n_in,
                              void* d_out, int out_size) {
    const int* loc = (const int*)d_in[0];
    const int* tim = (const int*)d_in[1];
    const int* clu = (const int*)d_in[2];
    const int* uid = (const int*)d_in[3];
    const float* emb_loc = (const float*)d_in[5];
    const float* emb_tim = (const float*)d_in[6];
    const float* emb_clu = (const float*)d_in[7];
    const float* emb_uid = (const float*)d_in[8];
    const float* eWih = (const float*)d_in[9];
    const float* eWhh = (const float*)d_in[10];
    const float* ebih = (const float*)d_in[11];
    const float* ebhh = (const float*)d_in[12];
    const float* dWih = (const float*)d_in[13];
    const float* dWhh = (const float*)d_in[14];
    const float* dbih = (const float*)d_in[15];
    const float* dbhh = (const float*)d_in[16];
    const float* fcW = (const float*)d_in[17];
    const float* fcb = (const float*)d_in[18];
    float* out = (float*)d_out;

    float *ppe, *ppd, *phh, *phd, *pat, *pcx, *py;
    cudaGetSymbolAddress((void**)&ppe, g_pre_enc);
    cudaGetSymbolAddress((void**)&ppd, g_pre_dec);
    cudaGetSymbolAddress((void**)&phh, g_hh);
    cudaGetSymbolAddress((void**)&phd, g_hd);
    cudaGetSymbolAddress((void**)&pat, g_attn);
    cudaGetSymbolAddress((void**)&pcx, g_ctx);
    cudaGetSymbolAddress((void**)&py,  g_y);
    __nv_bfloat16 *pfcb, *phhb, *phdb, *phhTb, *patb, *potb;
    cudaGetSymbolAddress((void**)&pfcb,  g_fcWb);
    cudaGetSymbolAddress((void**)&phhb,  g_hhb);
    cudaGetSymbolAddress((void**)&phdb,  g_hdb);
    cudaGetSymbolAddress((void**)&phhTb, g_hhTb);
    cudaGetSymbolAddress((void**)&patb,  g_attnb);
    cudaGetSymbolAddress((void**)&potb,  g_outb);

    // 0. embed -> bf16 x; sentinel fill (for fallback path)
    embed_kernel<<<S_LEN, 152>>>(loc, tim, clu, emb_loc, emb_tim, emb_clu);
    // 1. Wih conversions
    f2bw_kernel<<<1216, 256>>>(eWih, dWih);
    // 2. both input projections
    gemm_pre<<<dim3(G_DIM / 128, 40), 256>>>(ppe, ppd, ebih, ebhh, dbih, dbhh);

    // 3. LSTMs: cluster-DSMEM path if 16-CTA clusters supported, else L2 path
    cudaLaunchAttribute cattr[1];
    cattr[0].id = cudaLaunchAttributeClusterDimension;
    cattr[0].val.clusterDim.x = CL; cattr[0].val.clusterDim.y = 1;
    cattr[0].val.clusterDim.z = 1;
    cudaLaunchConfig_t cfg = {};
    cfg.gridDim = dim3(2 * CL, 1, 1);
    cfg.blockDim = dim3(256, 1, 1);
    cfg.dynamicSmemBytes = 0;
    cfg.stream = 0;
    cfg.attrs = cattr;
    cfg.numAttrs = 1;
    cudaError_t ra = cudaFuncSetAttribute(
        lstm_cluster_kernel, cudaFuncAttributeNonPortableClusterSizeAllowed, 1);
    int ncl = 0;
    cudaError_t rb = cudaOccupancyMaxActiveClusters(&ncl, lstm_cluster_kernel, &cfg);
    (void)cudaGetLastError();
    if (ra == cudaSuccess && rb == cudaSuccess && ncl >= 2) {
        cudaLaunchKernelEx(&cfg, lstm_cluster_kernel, (const float*)ppe, eWhh,
                           (const float*)ppd, dWhh);
    } else {
        lstm_fused_kernel<<<2 * NB, 256>>>(ppe, eWhh, phh, ppd, dWhh, phd);
    }

    // 4. fcW conversion
    f2b16_kernel<<<(LOC_N * FC_K / 16 + 255) / 256, 256>>>(fcW, pfcb, LOC_N * FC_K);
    // 5. attention scores = hd @ hh^T
    gemm_tc<<<dim3(SH_LEN / 128, T_LEN / 128), 256>>>(phdb, phhb, pat, nullptr, nullptr,
                                                      SH_LEN, H_DIM);
    // 6. softmax rows -> bf16
    softmax_kernel<<<T_LEN, 256>>>();
    // 7. context = attn @ hh
    gemm_tc<<<dim3(H_DIM / 128, T_LEN / 128), 256>>>(patb, phhTb, pcx, nullptr, nullptr,
                                                     H_DIM, SH_LEN);
    // 8. concat -> bf16
    concat_kernel<<<T_LEN, 272>>>(emb_uid, uid);
    // 9. FC: y = outc @ fcW^T + fcb
    gemm_tc<<<dim3((LOC_N + 127) / 128, T_LEN / 128), 256>>>(potb, pfcb, py, fcb, nullptr,
                                                             LOC_N, FC_K);
    // 10. log_softmax -> output
    logsoftmax_kernel<<<T_LEN, 512>>>(out);
}